// round 10
// baseline (speedup 1.0000x reference)
#include <cuda_runtime.h>
#include <cstdint>

// Flow1: K=32, B=4096, ZS=128, ZH=64, HS=50, NF=2
#define KK   32
#define BB   4096
#define ZSv  128
#define ZHv  64
#define HSv  50
#define ROWS (KK*BB)          // 131072
#define TPB  256              // 8 warps: 4 M-stripes (16 rows) x 2 N-halves
#define MT   64               // rows per CTA
#define NBLK (ROWS/MT)        // 2048
#define ZMSTR 132             // z master stride (conflict-free fragment loads)

// smem float-index offsets
#define ZM_OFF   0                       // z master [64][132] fp32
#define H_OFF    (MT*ZMSTR)              // 8448: h tile (tf32-rna) [64][64]
#define W0HI_OFF (H_OFF + MT*64)         // 12544: W0 hi (trunc) [56][64]
#define W0LO_OFF (W0HI_OFF + 3584)       // 16128: W0 lo resid [56][64]
#define W1T_OFF  (W0LO_OFF + 3584)       // 19712: W1 (rna tf32) [64][64]
#define W2T_OFF  (W1T_OFF + 4096)        // 23808: W2 (rna tf32)
#define BIAS_OFF (W2T_OFF + 4096)        // 27904: b0[64] b1[64] b2[64]
#define SMEM_FLOATS (BIAS_OFF + 192)     // 28096
#define SMEM_BYTES  (SMEM_FLOATS * 4)    // 112384 -> 2 CTAs/SM
#define RP_OFF   W0HI_OFF                // rowpart [64][4] (prologue only)
#define LG_OFF   H_OFF                   // lgpart [2][64] (epilogue only)

__device__ __forceinline__ uint32_t tf32_rna_bits(float x) {
    uint32_t u; asm("cvt.rna.tf32.f32 %0, %1;" : "=r"(u) : "f"(x));
    return u;
}
__device__ __forceinline__ float truncm(float x) {
    return __uint_as_float(__float_as_uint(x) & 0xFFFFE000u);
}
__device__ __forceinline__ float tanha(float x) {
    float y; asm("tanh.approx.f32 %0, %1;" : "=f"(y) : "f"(x));
    return y;
}
__device__ __forceinline__ int idx8(int r, int c) {
    return r * 64 + (c ^ ((r & 7) << 2));
}
__device__ __forceinline__ void hmma(float (&d)[4],
                                     uint32_t a0, uint32_t a1, uint32_t a2, uint32_t a3,
                                     uint32_t b0, uint32_t b1) {
    asm volatile(
        "mma.sync.aligned.m16n8k8.row.col.f32.tf32.tf32.f32 "
        "{%0,%1,%2,%3}, {%4,%5,%6,%7}, {%8,%9}, {%0,%1,%2,%3};"
        : "+f"(d[0]), "+f"(d[1]), "+f"(d[2]), "+f"(d[3])
        : "r"(a0), "r"(a1), "r"(a2), "r"(a3), "r"(b0), "r"(b1));
}

__global__ void __launch_bounds__(TPB, 2) flow_mma5(
    const float* __restrict__ mean, const float* __restrict__ logvar,
    const float* __restrict__ eps,
    const float* __restrict__ W0, const float* __restrict__ b0,
    const float* __restrict__ W1, const float* __restrict__ b1,
    const float* __restrict__ W2, const float* __restrict__ b2,
    float* __restrict__ out)
{
    extern __shared__ float sm[];
    float* ZM    = sm + ZM_OFF;
    float* H     = sm + H_OFF;
    float* b0sh  = sm + BIAS_OFF;
    float* b1sh  = b0sh + 64;
    float* b2sh  = b1sh + 64;
    float* rowpart = sm + RP_OFF;
    float* lgpart  = sm + LG_OFF;

    const int tid   = threadIdx.x;
    const int lane  = tid & 31;
    const int warp  = tid >> 5;
    const int warpM = warp & 3;        // M stripe (16 rows)
    const int nhalf = warp >> 2;       // N half
    const int g     = lane >> 2;
    const int t     = lane & 3;
    const int rl    = warpM * 16 + g;  // fragment rows rl, rl+8
    const int ntbase = nhalf * 4;
    const size_t r0    = (size_t)blockIdx.x * MT;
    const size_t bbase = (size_t)(r0 & (BB-1)) * ZSv;

    // ---------------- prologue: z = eps*exp(0.5*lv)+mean ; rowsum(lv+eps^2) ----
    #pragma unroll 4
    for (int it = 0; it < 32; it++) {
        int j   = it*2 + (tid >> 7);
        int col = tid & 127;
        size_t go = (size_t)j * ZSv + col;
        float ep = eps[r0*ZSv + go];
        float lv = logvar[bbase + go];
        float mn = mean[bbase + go];
        ZM[j*ZMSTR + col] = fmaf(ep, __expf(0.5f*lv), mn);
        float c = fmaf(ep, ep, lv);
        #pragma unroll
        for (int o = 16; o; o >>= 1) c += __shfl_xor_sync(0xFFFFFFFFu, c, o);
        if (lane == 0) rowpart[j*4 + ((tid >> 5) & 3)] = c;
    }
    __syncthreads();
    float rsum = 0.f;
    if (tid < 64)
        rsum = rowpart[tid*4+0] + rowpart[tid*4+1] + rowpart[tid*4+2] + rowpart[tid*4+3];

    float lgr[2] = {0.f, 0.f};

    const uint32_t* w0hiU = (const uint32_t*)(sm + W0HI_OFF);
    const uint32_t* w0loU = (const uint32_t*)(sm + W0LO_OFF);
    const uint32_t* w1tU  = (const uint32_t*)(sm + W1T_OFF);
    const uint32_t* w2tU  = (const uint32_t*)(sm + W2T_OFF);
    const uint32_t* hU    = (const uint32_t*)H;

    // ---------------- 4 flow half-steps ---------------------------------------
    #pragma unroll 1
    for (int s = 0; s < 4; s++) {
        __syncthreads();
        {   // stage weights (W0 hi/lo compensated, 56 rows; W1/W2 rna), padded
            const float* W0g = W0 + s*(HSv*ZHv);
            #pragma unroll 1
            for (int i = tid; i < 56*64; i += TPB) {
                int n = i >> 6, k = i & 63;
                float v = (n < HSv) ? W0g[n*ZHv + k] : 0.f;
                float hi = truncm(v);
                int ix = idx8(n, k);
                sm[W0HI_OFF + ix] = hi;
                sm[W0LO_OFF + ix] = __uint_as_float(tf32_rna_bits(v - hi));
            }
            const float* W1g = W1 + s*(ZHv*HSv);
            const float* W2g = W2 + s*(ZHv*HSv);
            #pragma unroll 1
            for (int i = tid; i < 64*64; i += TPB) {
                int n = i >> 6, k = i & 63;
                float v1 = (k < HSv) ? W1g[n*HSv + k] : 0.f;
                float v2 = (k < HSv) ? W2g[n*HSv + k] : 0.f;
                int ix = idx8(n, k);
                sm[W1T_OFF + ix] = __uint_as_float(tf32_rna_bits(v1));
                sm[W2T_OFF + ix] = __uint_as_float(tf32_rna_bits(v2));
            }
            if (tid < 64) {
                b0sh[tid] = (tid < HSv) ? b0[s*HSv + tid] : 0.f;
                b1sh[tid] = b1[s*ZHv + tid];
                b2sh[tid] = b2[s*ZHv + tid];
            }
        }
        __syncthreads();

        const int srcoff = (s & 1) ? 64 : 0;
        const int tgtoff = 64 - srcoff;

        // ======== GEMM0: h = tanh(z_src @ W0^T + b0), compensated ==============
        // z-lo fragments computed on the fly from fp32 ZM (no ZLO tile).
        {
            float acc[4][4];
            #pragma unroll
            for (int nn = 0; nn < 4; nn++)
                #pragma unroll
                for (int v = 0; v < 4; v++) acc[nn][v] = 0.f;

            const int nlim = (nhalf == 1) ? 3 : 4;   // skip all-zero nt==7

            #pragma unroll
            for (int kt = 0; kt < 8; kt++) {
                const int kc = srcoff + kt*8 + t;
                const int kz = kt*8 + t;
                const int rh = rl + 8;
                float zv0 = ZM[rl*ZMSTR + kc];
                float zv1 = ZM[rh*ZMSTR + kc];
                float zv2 = ZM[rl*ZMSTR + kc+4];
                float zv3 = ZM[rh*ZMSTR + kc+4];
                uint32_t am0 = __float_as_uint(zv0) & 0xFFFFE000u;
                uint32_t am1 = __float_as_uint(zv1) & 0xFFFFE000u;
                uint32_t am2 = __float_as_uint(zv2) & 0xFFFFE000u;
                uint32_t am3 = __float_as_uint(zv3) & 0xFFFFE000u;
                uint32_t zl0 = __float_as_uint(zv0 - __uint_as_float(am0)) & 0xFFFFE000u;
                uint32_t zl1 = __float_as_uint(zv1 - __uint_as_float(am1)) & 0xFFFFE000u;
                uint32_t zl2 = __float_as_uint(zv2 - __uint_as_float(am2)) & 0xFFFFE000u;
                uint32_t zl3 = __float_as_uint(zv3 - __uint_as_float(am3)) & 0xFFFFE000u;
                #pragma unroll
                for (int nn = 0; nn < 4; nn++) {
                    if (nn >= nlim) break;
                    const int n = (ntbase + nn)*8 + g;
                    const uint32_t bh0 = w0hiU[idx8(n, kz)];
                    const uint32_t bh1 = w0hiU[idx8(n, kz+4)];
                    const uint32_t bl0 = w0loU[idx8(n, kz)];
                    const uint32_t bl1 = w0loU[idx8(n, kz+4)];
                    hmma(acc[nn], am0, am1, am2, am3, bh0, bh1);
                    hmma(acc[nn], am0, am1, am2, am3, bl0, bl1);
                    hmma(acc[nn], zl0, zl1, zl2, zl3, bh0, bh1);
                }
            }
            // tanh epilogue -> H (tf32-rna); zero tile for nt==7
            #pragma unroll
            for (int nn = 0; nn < 4; nn++) {
                const int cb = (ntbase + nn)*8 + 2*t;
                const int rh = rl + 8;
                if (nn >= ((nhalf == 1) ? 3 : 4)) {
                    *(float2*)(H + idx8(rl, cb)) = make_float2(0.f, 0.f);
                    *(float2*)(H + idx8(rh, cb)) = make_float2(0.f, 0.f);
                } else {
                    float h00 = tanha(acc[nn][0] + b0sh[cb]);
                    float h01 = tanha(acc[nn][1] + b0sh[cb+1]);
                    float h10 = tanha(acc[nn][2] + b0sh[cb]);
                    float h11 = tanha(acc[nn][3] + b0sh[cb+1]);
                    *(float2*)(H + idx8(rl, cb)) = make_float2(
                        __uint_as_float(tf32_rna_bits(h00)),
                        __uint_as_float(tf32_rna_bits(h01)));
                    *(float2*)(H + idx8(rh, cb)) = make_float2(
                        __uint_as_float(tf32_rna_bits(h10)),
                        __uint_as_float(tf32_rna_bits(h11)));
                }
            }
        }
        __syncthreads();   // H complete (cross-warp consumption next)

        // ======== GEMM1/2: mew, sr ; update target half + logdet ===============
        #pragma unroll
        for (int grp = 0; grp < 2; grp++) {
            const int nt0 = ntbase + grp*2;
            float am2a[2][4], av2a[2][4];
            #pragma unroll
            for (int nn = 0; nn < 2; nn++)
                #pragma unroll
                for (int v = 0; v < 4; v++) { am2a[nn][v] = 0.f; av2a[nn][v] = 0.f; }

            #pragma unroll
            for (int kt = 0; kt < 7; kt++) {      // k-tile 7 all-zero: skipped
                const int k0 = kt*8 + t;
                const int rh = rl + 8;
                const uint32_t hf0 = hU[idx8(rl, k0)];
                const uint32_t hf1 = hU[idx8(rh, k0)];
                const uint32_t hf2 = hU[idx8(rl, k0+4)];
                const uint32_t hf3 = hU[idx8(rh, k0+4)];
                #pragma unroll
                for (int nn = 0; nn < 2; nn++) {
                    const int n = (nt0 + nn)*8 + g;
                    const uint32_t c1h0 = w1tU[idx8(n, k0)], c1h1 = w1tU[idx8(n, k0+4)];
                    const uint32_t c2h0 = w2tU[idx8(n, k0)], c2h1 = w2tU[idx8(n, k0+4)];
                    hmma(am2a[nn], hf0, hf1, hf2, hf3, c1h0, c1h1);
                    hmma(av2a[nn], hf0, hf1, hf2, hf3, c2h0, c2h1);
                }
            }
            // update epilogue
            #pragma unroll
            for (int nn = 0; nn < 2; nn++) {
                const int cb = (nt0 + nn)*8 + 2*t;
                #pragma unroll
                for (int hh = 0; hh < 2; hh++) {
                    const int r = rl + 8*hh;
                    const float mew0 = am2a[nn][2*hh+0] + b1sh[cb];
                    const float mew1 = am2a[nn][2*hh+1] + b1sh[cb+1];
                    const float sr0  = av2a[nn][2*hh+0] + b2sh[cb];
                    const float sr1  = av2a[nn][2*hh+1] + b2sh[cb+1];
                    const float e0 = __expf(-sr0), e1 = __expf(-sr1);
                    const float o0 = 1.f + e0,     o1 = 1.f + e1;
                    const float g0 = __fdividef(1.f, o0);
                    const float g1 = __fdividef(1.f, o1);
                    lgr[hh] += __log2f(o0) + __log2f(o1);
                    float2 zo = *(const float2*)(ZM + r*ZMSTR + tgtoff + cb);
                    const float zn0 = fmaf(zo.x, g0, mew0);
                    const float zn1 = fmaf(zo.y, g1, mew1);
                    *(float2*)(ZM + r*ZMSTR + tgtoff + cb) = make_float2(zn0, zn1);
                }
            }
        }
    }

    // ---------------- logdet reduce (lgpart unions dead H) ---------------------
    __syncthreads();
    #pragma unroll
    for (int i = 0; i < 2; i++) {
        float v = lgr[i];
        v += __shfl_xor_sync(0xFFFFFFFFu, v, 1);
        v += __shfl_xor_sync(0xFFFFFFFFu, v, 2);
        if (t == 0)
            lgpart[nhalf*64 + warpM*16 + i*8 + g] = v;
    }
    __syncthreads();

    // ---------------- epilogue: z_out + logpz ----------------------------------
    #pragma unroll 4
    for (int it = 0; it < 32; it++) {
        int j   = it*2 + (tid >> 7);
        int col = tid & 127;
        out[(r0 + j)*ZSv + col] = ZM[j*ZMSTR + col];
    }
    if (tid < 64) {
        float lg = lgpart[tid] + lgpart[64 + tid];
        float logq = -0.5f * ((float)ZSv * 1.8378770664093453f + rsum);
        out[(size_t)ROWS*ZSv + r0 + tid] = logq + 0.69314718055994531f * lg;
    }
}

extern "C" void kernel_launch(void* const* d_in, const int* in_sizes, int n_in,
                              void* d_out, int out_size) {
    (void)in_sizes; (void)n_in; (void)out_size;
    const float* mean   = (const float*)d_in[0];
    const float* logvar = (const float*)d_in[1];
    const float* eps    = (const float*)d_in[2];
    const float* W0     = (const float*)d_in[3];
    const float* b0     = (const float*)d_in[4];
    const float* W1     = (const float*)d_in[5];
    const float* b1     = (const float*)d_in[6];
    const float* W2     = (const float*)d_in[7];
    const float* b2     = (const float*)d_in[8];
    float* out = (float*)d_out;

    cudaFuncSetAttribute(flow_mma5, cudaFuncAttributeMaxDynamicSharedMemorySize, SMEM_BYTES);
    flow_mma5<<<NBLK, TPB, SMEM_BYTES>>>(mean, logvar, eps, W0, b0, W1, b1, W2, b2, out);
}

// round 11
// speedup vs baseline: 1.3094x; 1.3094x over previous
#include <cuda_runtime.h>
#include <cstdint>

// Flow1: K=32, B=4096, ZS=128, ZH=64, HS=50, NF=2
#define KK   32
#define BB   4096
#define ZSv  128
#define ZHv  64
#define HSv  50
#define ROWS (KK*BB)          // 131072
#define TPB  512              // 16 warps: 8 M-stripes (16 rows) x 2 N-halves
#define MT   128              // rows per CTA
#define NBLK (ROWS/MT)        // 1024
#define ZMSTR 132             // z master stride

// smem float-index offsets
#define ZM_OFF   0                       // z master [128][132] fp32
#define H_OFF    (MT*ZMSTR)              // 16896: h tile (tf32-rna) [128][64]
#define W0HI_OFF (H_OFF + MT*64)         // 25088: W0 hi (trunc) [56][64]
#define W0LO_OFF (W0HI_OFF + 3584)       // 28672: W0 lo resid
#define W1T_OFF  (W0LO_OFF + 3584)       // 32256: W1 (rna tf32) [64][64]
#define W2T_OFF  (W1T_OFF + 4096)        // 36352: W2 (rna tf32)
#define BIAS_OFF (W2T_OFF + 4096)        // 40448: b0[64] b1[64] b2[64]
#define SMEM_FLOATS (BIAS_OFF + 192)     // 40640
#define SMEM_BYTES  (SMEM_FLOATS * 4)    // 162560 -> 1 CTA/SM
#define RP_OFF   W0HI_OFF                // rowpart [128][4] (prologue only)
#define LG_OFF   H_OFF                   // lgpart [2][128] (epilogue only)

// pre-converted weights (filled by prep kernel each launch; deterministic)
__device__ __align__(16) float gW0hi[4][3584];
__device__ __align__(16) float gW0lo[4][3584];
__device__ __align__(16) float gW1t [4][4096];
__device__ __align__(16) float gW2t [4][4096];
__device__ __align__(16) float gBias[4][192];

__device__ __forceinline__ uint32_t tf32_rna_bits(float x) {
    uint32_t u; asm("cvt.rna.tf32.f32 %0, %1;" : "=r"(u) : "f"(x));
    return u;
}
__device__ __forceinline__ float truncm(float x) {
    return __uint_as_float(__float_as_uint(x) & 0xFFFFE000u);
}
__device__ __forceinline__ float tanha(float x) {
    float y; asm("tanh.approx.f32 %0, %1;" : "=f"(y) : "f"(x));
    return y;
}
__device__ __forceinline__ int idx8(int r, int c) {
    return r * 64 + (c ^ ((r & 7) << 2));
}
__device__ __forceinline__ void hmma(float (&d)[4],
                                     uint32_t a0, uint32_t a1, uint32_t a2, uint32_t a3,
                                     uint32_t b0, uint32_t b1) {
    asm volatile(
        "mma.sync.aligned.m16n8k8.row.col.f32.tf32.tf32.f32 "
        "{%0,%1,%2,%3}, {%4,%5,%6,%7}, {%8,%9}, {%0,%1,%2,%3};"
        : "+f"(d[0]), "+f"(d[1]), "+f"(d[2]), "+f"(d[3])
        : "r"(a0), "r"(a1), "r"(a2), "r"(a3), "r"(b0), "r"(b1));
}

// ---- prep: convert weights once (4 CTAs, one per half-step) -----------------
__global__ void flow_prep(const float* __restrict__ W0, const float* __restrict__ b0,
                          const float* __restrict__ W1, const float* __restrict__ b1,
                          const float* __restrict__ W2, const float* __restrict__ b2)
{
    const int s = blockIdx.x;
    const int tid = threadIdx.x;
    const float* W0g = W0 + s*(HSv*ZHv);
    for (int i = tid; i < 56*64; i += blockDim.x) {
        int n = i >> 6, k = i & 63;
        float v = (n < HSv) ? W0g[n*ZHv + k] : 0.f;
        float hi = truncm(v);
        int ix = idx8(n, k);
        gW0hi[s][ix] = hi;
        gW0lo[s][ix] = __uint_as_float(tf32_rna_bits(v - hi));
    }
    const float* W1g = W1 + s*(ZHv*HSv);
    const float* W2g = W2 + s*(ZHv*HSv);
    for (int i = tid; i < 64*64; i += blockDim.x) {
        int n = i >> 6, k = i & 63;
        float v1 = (k < HSv) ? W1g[n*HSv + k] : 0.f;
        float v2 = (k < HSv) ? W2g[n*HSv + k] : 0.f;
        int ix = idx8(n, k);
        gW1t[s][ix] = __uint_as_float(tf32_rna_bits(v1));
        gW2t[s][ix] = __uint_as_float(tf32_rna_bits(v2));
    }
    if (tid < 64) {
        gBias[s][tid]       = (tid < HSv) ? b0[s*HSv + tid] : 0.f;
        gBias[s][64 + tid]  = b1[s*ZHv + tid];
        gBias[s][128 + tid] = b2[s*ZHv + tid];
    }
}

// ---- main flow kernel --------------------------------------------------------
__global__ void __launch_bounds__(TPB, 1) flow_mma6(
    const float* __restrict__ mean, const float* __restrict__ logvar,
    const float* __restrict__ eps, float* __restrict__ out)
{
    extern __shared__ float sm[];
    float* ZM    = sm + ZM_OFF;
    float* H     = sm + H_OFF;
    float* b0sh  = sm + BIAS_OFF;
    float* b1sh  = b0sh + 64;
    float* b2sh  = b1sh + 64;
    float* rowpart = sm + RP_OFF;
    float* lgpart  = sm + LG_OFF;

    const int tid   = threadIdx.x;
    const int lane  = tid & 31;
    const int warp  = tid >> 5;
    const int warpM = warp & 7;        // M stripe (16 rows)
    const int nhalf = warp >> 3;       // N half
    const int g     = lane >> 2;
    const int t     = lane & 3;
    const int rl    = warpM * 16 + g;  // fragment rows rl, rl+8
    const int ntbase = nhalf * 4;
    const size_t r0    = (size_t)blockIdx.x * MT;
    const size_t bbase = (size_t)(r0 & (BB-1)) * ZSv;

    // ---------------- prologue: z = eps*exp(0.5*lv)+mean ; rowsum(lv+eps^2) ----
    #pragma unroll 4
    for (int it = 0; it < 32; it++) {
        int j   = it*4 + (tid >> 7);
        int col = tid & 127;
        size_t go = (size_t)j * ZSv + col;
        float ep = eps[r0*ZSv + go];
        float lv = logvar[bbase + go];
        float mn = mean[bbase + go];
        ZM[j*ZMSTR + col] = fmaf(ep, __expf(0.5f*lv), mn);
        float c = fmaf(ep, ep, lv);
        #pragma unroll
        for (int o = 16; o; o >>= 1) c += __shfl_xor_sync(0xFFFFFFFFu, c, o);
        if (lane == 0) rowpart[j*4 + ((tid >> 5) & 3)] = c;
    }
    __syncthreads();
    float rsum = 0.f;
    if (tid < 128)
        rsum = rowpart[tid*4+0] + rowpart[tid*4+1] + rowpart[tid*4+2] + rowpart[tid*4+3];

    float lgr[2] = {0.f, 0.f};

    const uint32_t* w0hiU = (const uint32_t*)(sm + W0HI_OFF);
    const uint32_t* w0loU = (const uint32_t*)(sm + W0LO_OFF);
    const uint32_t* w1tU  = (const uint32_t*)(sm + W1T_OFF);
    const uint32_t* w2tU  = (const uint32_t*)(sm + W2T_OFF);
    const uint32_t* hU    = (const uint32_t*)H;

    // ---------------- 4 flow half-steps ---------------------------------------
    #pragma unroll 1
    for (int s = 0; s < 4; s++) {
        __syncthreads();
        {   // stage pre-converted weights: pure float4 copies
            float4* dst = (float4*)(sm + W0HI_OFF);
            const float4* s0h = (const float4*)gW0hi[s];
            const float4* s0l = (const float4*)gW0lo[s];
            const float4* s1  = (const float4*)gW1t[s];
            const float4* s2  = (const float4*)gW2t[s];
            #pragma unroll 1
            for (int i = tid; i < 896; i += TPB) dst[i] = s0h[i];
            float4* dlo = (float4*)(sm + W0LO_OFF);
            #pragma unroll 1
            for (int i = tid; i < 896; i += TPB) dlo[i] = s0l[i];
            float4* d1 = (float4*)(sm + W1T_OFF);
            #pragma unroll 1
            for (int i = tid; i < 1024; i += TPB) d1[i] = s1[i];
            float4* d2 = (float4*)(sm + W2T_OFF);
            #pragma unroll 1
            for (int i = tid; i < 1024; i += TPB) d2[i] = s2[i];
            if (tid < 192) sm[BIAS_OFF + tid] = gBias[s][tid];
        }
        __syncthreads();

        const int srcoff = (s & 1) ? 64 : 0;
        const int tgtoff = 64 - srcoff;

        // ======== GEMM0: h = tanh(z_src @ W0^T + b0), compensated ==============
        // z-lo fragments computed on the fly from fp32 ZM.
        {
            float acc[4][4];
            #pragma unroll
            for (int nn = 0; nn < 4; nn++)
                #pragma unroll
                for (int v = 0; v < 4; v++) acc[nn][v] = 0.f;

            const int nlim = (nhalf == 1) ? 3 : 4;   // skip all-zero nt==7

            #pragma unroll
            for (int kt = 0; kt < 8; kt++) {
                const int kz = kt*8 + t;
                const int kc = srcoff + kz;
                const int rh = rl + 8;
                float zv0 = ZM[rl*ZMSTR + kc];
                float zv1 = ZM[rh*ZMSTR + kc];
                float zv2 = ZM[rl*ZMSTR + kc+4];
                float zv3 = ZM[rh*ZMSTR + kc+4];
                uint32_t am0 = __float_as_uint(zv0) & 0xFFFFE000u;
                uint32_t am1 = __float_as_uint(zv1) & 0xFFFFE000u;
                uint32_t am2 = __float_as_uint(zv2) & 0xFFFFE000u;
                uint32_t am3 = __float_as_uint(zv3) & 0xFFFFE000u;
                uint32_t zl0 = __float_as_uint(zv0 - __uint_as_float(am0)) & 0xFFFFE000u;
                uint32_t zl1 = __float_as_uint(zv1 - __uint_as_float(am1)) & 0xFFFFE000u;
                uint32_t zl2 = __float_as_uint(zv2 - __uint_as_float(am2)) & 0xFFFFE000u;
                uint32_t zl3 = __float_as_uint(zv3 - __uint_as_float(am3)) & 0xFFFFE000u;
                #pragma unroll
                for (int nn = 0; nn < 4; nn++) {
                    if (nn >= nlim) break;
                    const int n = (ntbase + nn)*8 + g;
                    const uint32_t bh0 = w0hiU[idx8(n, kz)];
                    const uint32_t bh1 = w0hiU[idx8(n, kz+4)];
                    const uint32_t bl0 = w0loU[idx8(n, kz)];
                    const uint32_t bl1 = w0loU[idx8(n, kz+4)];
                    hmma(acc[nn], am0, am1, am2, am3, bh0, bh1);
                    hmma(acc[nn], am0, am1, am2, am3, bl0, bl1);
                    hmma(acc[nn], zl0, zl1, zl2, zl3, bh0, bh1);
                }
            }
            // tanh epilogue -> H (tf32-rna); zero tile for nt==7
            #pragma unroll
            for (int nn = 0; nn < 4; nn++) {
                const int cb = (ntbase + nn)*8 + 2*t;
                const int rh = rl + 8;
                if (nn >= ((nhalf == 1) ? 3 : 4)) {
                    *(float2*)(H + idx8(rl, cb)) = make_float2(0.f, 0.f);
                    *(float2*)(H + idx8(rh, cb)) = make_float2(0.f, 0.f);
                } else {
                    float h00 = tanha(acc[nn][0] + b0sh[cb]);
                    float h01 = tanha(acc[nn][1] + b0sh[cb+1]);
                    float h10 = tanha(acc[nn][2] + b0sh[cb]);
                    float h11 = tanha(acc[nn][3] + b0sh[cb+1]);
                    *(float2*)(H + idx8(rl, cb)) = make_float2(
                        __uint_as_float(tf32_rna_bits(h00)),
                        __uint_as_float(tf32_rna_bits(h01)));
                    *(float2*)(H + idx8(rh, cb)) = make_float2(
                        __uint_as_float(tf32_rna_bits(h10)),
                        __uint_as_float(tf32_rna_bits(h11)));
                }
            }
        }
        __syncthreads();   // H complete (cross-warp consumption next)

        // ======== GEMM1/2: mew, sr ; update target half + logdet ===============
        #pragma unroll
        for (int grp = 0; grp < 2; grp++) {
            const int nt0 = ntbase + grp*2;
            float am2a[2][4], av2a[2][4];
            #pragma unroll
            for (int nn = 0; nn < 2; nn++)
                #pragma unroll
                for (int v = 0; v < 4; v++) { am2a[nn][v] = 0.f; av2a[nn][v] = 0.f; }

            #pragma unroll
            for (int kt = 0; kt < 7; kt++) {      // k-tile 7 all-zero: skipped
                const int k0 = kt*8 + t;
                const int rh = rl + 8;
                const uint32_t hf0 = hU[idx8(rl, k0)];
                const uint32_t hf1 = hU[idx8(rh, k0)];
                const uint32_t hf2 = hU[idx8(rl, k0+4)];
                const uint32_t hf3 = hU[idx8(rh, k0+4)];
                #pragma unroll
                for (int nn = 0; nn < 2; nn++) {
                    const int n = (nt0 + nn)*8 + g;
                    const uint32_t c1h0 = w1tU[idx8(n, k0)], c1h1 = w1tU[idx8(n, k0+4)];
                    const uint32_t c2h0 = w2tU[idx8(n, k0)], c2h1 = w2tU[idx8(n, k0+4)];
                    hmma(am2a[nn], hf0, hf1, hf2, hf3, c1h0, c1h1);
                    hmma(av2a[nn], hf0, hf1, hf2, hf3, c2h0, c2h1);
                }
            }
            // update epilogue
            #pragma unroll
            for (int nn = 0; nn < 2; nn++) {
                const int cb = (nt0 + nn)*8 + 2*t;
                #pragma unroll
                for (int hh = 0; hh < 2; hh++) {
                    const int r = rl + 8*hh;
                    const float mew0 = am2a[nn][2*hh+0] + b1sh[cb];
                    const float mew1 = am2a[nn][2*hh+1] + b1sh[cb+1];
                    const float sr0  = av2a[nn][2*hh+0] + b2sh[cb];
                    const float sr1  = av2a[nn][2*hh+1] + b2sh[cb+1];
                    const float e0 = __expf(-sr0), e1 = __expf(-sr1);
                    const float o0 = 1.f + e0,     o1 = 1.f + e1;
                    const float g0 = __fdividef(1.f, o0);
                    const float g1 = __fdividef(1.f, o1);
                    lgr[hh] += __log2f(o0) + __log2f(o1);
                    float2 zo = *(const float2*)(ZM + r*ZMSTR + tgtoff + cb);
                    const float zn0 = fmaf(zo.x, g0, mew0);
                    const float zn1 = fmaf(zo.y, g1, mew1);
                    *(float2*)(ZM + r*ZMSTR + tgtoff + cb) = make_float2(zn0, zn1);
                }
            }
        }
    }

    // ---------------- logdet reduce (lgpart unions dead H) ---------------------
    __syncthreads();
    #pragma unroll
    for (int i = 0; i < 2; i++) {
        float v = lgr[i];
        v += __shfl_xor_sync(0xFFFFFFFFu, v, 1);
        v += __shfl_xor_sync(0xFFFFFFFFu, v, 2);
        if (t == 0)
            lgpart[nhalf*128 + warpM*16 + i*8 + g] = v;
    }
    __syncthreads();

    // ---------------- epilogue: z_out + logpz ----------------------------------
    #pragma unroll 4
    for (int it = 0; it < 32; it++) {
        int j   = it*4 + (tid >> 7);
        int col = tid & 127;
        out[(r0 + j)*ZSv + col] = ZM[j*ZMSTR + col];
    }
    if (tid < 128) {
        float lg = lgpart[tid] + lgpart[128 + tid];
        float logq = -0.5f * ((float)ZSv * 1.8378770664093453f + rsum);
        out[(size_t)ROWS*ZSv + r0 + tid] = logq + 0.69314718055994531f * lg;
    }
}

extern "C" void kernel_launch(void* const* d_in, const int* in_sizes, int n_in,
                              void* d_out, int out_size) {
    (void)in_sizes; (void)n_in; (void)out_size;
    const float* mean   = (const float*)d_in[0];
    const float* logvar = (const float*)d_in[1];
    const float* eps    = (const float*)d_in[2];
    const float* W0     = (const float*)d_in[3];
    const float* b0     = (const float*)d_in[4];
    const float* W1     = (const float*)d_in[5];
    const float* b1     = (const float*)d_in[6];
    const float* W2     = (const float*)d_in[7];
    const float* b2     = (const float*)d_in[8];
    float* out = (float*)d_out;

    flow_prep<<<4, 256>>>(W0, b0, W1, b1, W2, b2);
    cudaFuncSetAttribute(flow_mma6, cudaFuncAttributeMaxDynamicSharedMemorySize, SMEM_BYTES);
    flow_mma6<<<NBLK, TPB, SMEM_BYTES>>>(mean, logvar, eps, out);
}

// round 12
// speedup vs baseline: 1.4560x; 1.1119x over previous
#include <cuda_runtime.h>
#include <cstdint>

// Flow1: K=32, B=4096, ZS=128, ZH=64, HS=50, NF=2
#define KK   32
#define BB   4096
#define ZSv  128
#define ZHv  64
#define HSv  50
#define ROWS (KK*BB)          // 131072
#define TPB  512              // 16 warps: 4 M-stripes (32 rows) x 4 N-quarters
#define MT   128              // rows per CTA
#define NBLK (ROWS/MT)        // 1024
#define ZMSTR 132             // z master stride

// smem float-index offsets
#define ZM_OFF   0                       // z master [128][132] fp32
#define H_OFF    (MT*ZMSTR)              // 16896: h tile (tf32-rna) [128][64]
#define W0HI_OFF (H_OFF + MT*64)         // 25088: W0 hi (trunc) [56][64]
#define W0LO_OFF (W0HI_OFF + 3584)       // 28672: W0 lo resid
#define W1T_OFF  (W0LO_OFF + 3584)       // 32256: W1 (rna tf32) [64][64]
#define W2T_OFF  (W1T_OFF + 4096)        // 36352: W2 (rna tf32)
#define BIAS_OFF (W2T_OFF + 4096)        // 40448: b0[64] b1[64] b2[64]
#define SMEM_FLOATS (BIAS_OFF + 192)     // 40640
#define SMEM_BYTES  (SMEM_FLOATS * 4)    // 162560 -> 1 CTA/SM
#define RP_OFF   W0HI_OFF                // rowpart [128][4] (prologue only)
#define LG_OFF   H_OFF                   // lgpart [4][128] (epilogue only)

// pre-converted weights (filled by prep kernel each launch; deterministic)
__device__ __align__(16) float gW0hi[4][3584];
__device__ __align__(16) float gW0lo[4][3584];
__device__ __align__(16) float gW1t [4][4096];
__device__ __align__(16) float gW2t [4][4096];
__device__ __align__(16) float gBias[4][192];

__device__ __forceinline__ uint32_t tf32_rna_bits(float x) {
    uint32_t u; asm("cvt.rna.tf32.f32 %0, %1;" : "=r"(u) : "f"(x));
    return u;
}
__device__ __forceinline__ float truncm(float x) {
    return __uint_as_float(__float_as_uint(x) & 0xFFFFE000u);
}
__device__ __forceinline__ float tanha(float x) {
    float y; asm("tanh.approx.f32 %0, %1;" : "=f"(y) : "f"(x));
    return y;
}
__device__ __forceinline__ int idx8(int r, int c) {
    return r * 64 + (c ^ ((r & 7) << 2));
}
__device__ __forceinline__ void hmma(float (&d)[4],
                                     uint32_t a0, uint32_t a1, uint32_t a2, uint32_t a3,
                                     uint32_t b0, uint32_t b1) {
    asm volatile(
        "mma.sync.aligned.m16n8k8.row.col.f32.tf32.tf32.f32 "
        "{%0,%1,%2,%3}, {%4,%5,%6,%7}, {%8,%9}, {%0,%1,%2,%3};"
        : "+f"(d[0]), "+f"(d[1]), "+f"(d[2]), "+f"(d[3])
        : "r"(a0), "r"(a1), "r"(a2), "r"(a3), "r"(b0), "r"(b1));
}

// ---- prep: convert weights once (4 CTAs, one per half-step) -----------------
__global__ void flow_prep(const float* __restrict__ W0, const float* __restrict__ b0,
                          const float* __restrict__ W1, const float* __restrict__ b1,
                          const float* __restrict__ W2, const float* __restrict__ b2)
{
    const int s = blockIdx.x;
    const int tid = threadIdx.x;
    const float* W0g = W0 + s*(HSv*ZHv);
    for (int i = tid; i < 56*64; i += blockDim.x) {
        int n = i >> 6, k = i & 63;
        float v = (n < HSv) ? W0g[n*ZHv + k] : 0.f;
        float hi = truncm(v);
        int ix = idx8(n, k);
        gW0hi[s][ix] = hi;
        gW0lo[s][ix] = __uint_as_float(tf32_rna_bits(v - hi));
    }
    const float* W1g = W1 + s*(ZHv*HSv);
    const float* W2g = W2 + s*(ZHv*HSv);
    for (int i = tid; i < 64*64; i += blockDim.x) {
        int n = i >> 6, k = i & 63;
        float v1 = (k < HSv) ? W1g[n*HSv + k] : 0.f;
        float v2 = (k < HSv) ? W2g[n*HSv + k] : 0.f;
        int ix = idx8(n, k);
        gW1t[s][ix] = __uint_as_float(tf32_rna_bits(v1));
        gW2t[s][ix] = __uint_as_float(tf32_rna_bits(v2));
    }
    if (tid < 64) {
        gBias[s][tid]       = (tid < HSv) ? b0[s*HSv + tid] : 0.f;
        gBias[s][64 + tid]  = b1[s*ZHv + tid];
        gBias[s][128 + tid] = b2[s*ZHv + tid];
    }
}

// ---- main flow kernel --------------------------------------------------------
__global__ void __launch_bounds__(TPB, 1) flow_mma7(
    const float* __restrict__ mean, const float* __restrict__ logvar,
    const float* __restrict__ eps, float* __restrict__ out)
{
    extern __shared__ float sm[];
    float* ZM    = sm + ZM_OFF;
    float* H     = sm + H_OFF;
    float* b0sh  = sm + BIAS_OFF;
    float* b1sh  = b0sh + 64;
    float* b2sh  = b1sh + 64;
    float* rowpart = sm + RP_OFF;
    float* lgpart  = sm + LG_OFF;

    const int tid   = threadIdx.x;
    const int lane  = tid & 31;
    const int warp  = tid >> 5;
    const int warpM = warp & 3;        // M stripe (32 rows, m32 per warp)
    const int warpQ = warp >> 2;       // N quarter (2 n-tiles)
    const int g     = lane >> 2;
    const int t     = lane & 3;
    const int rl    = warpM * 32 + g;  // m16 block rows: rl,rl+8 ; rl+16,rl+24
    const int nt0   = warpQ * 2;
    const size_t r0    = (size_t)blockIdx.x * MT;
    const size_t bbase = (size_t)(r0 & (BB-1)) * ZSv;

    // ---------------- prologue: z = eps*exp(0.5*lv)+mean ; rowsum(lv+eps^2) ----
    #pragma unroll 4
    for (int it = 0; it < 32; it++) {
        int j   = it*4 + (tid >> 7);
        int col = tid & 127;
        size_t go = (size_t)j * ZSv + col;
        float ep = eps[r0*ZSv + go];
        float lv = logvar[bbase + go];
        float mn = mean[bbase + go];
        ZM[j*ZMSTR + col] = fmaf(ep, __expf(0.5f*lv), mn);
        float c = fmaf(ep, ep, lv);
        #pragma unroll
        for (int o = 16; o; o >>= 1) c += __shfl_xor_sync(0xFFFFFFFFu, c, o);
        if (lane == 0) rowpart[j*4 + ((tid >> 5) & 3)] = c;
    }
    __syncthreads();
    float rsum = 0.f;
    if (tid < 128)
        rsum = rowpart[tid*4+0] + rowpart[tid*4+1] + rowpart[tid*4+2] + rowpart[tid*4+3];

    float lgr[4] = {0.f, 0.f, 0.f, 0.f};   // [mb*2+hh]: rows rl+16mb+8hh

    const uint32_t* w0hiU = (const uint32_t*)(sm + W0HI_OFF);
    const uint32_t* w0loU = (const uint32_t*)(sm + W0LO_OFF);
    const uint32_t* w1tU  = (const uint32_t*)(sm + W1T_OFF);
    const uint32_t* w2tU  = (const uint32_t*)(sm + W2T_OFF);
    const uint32_t* hU    = (const uint32_t*)H;

    // ---------------- 4 flow half-steps ---------------------------------------
    #pragma unroll 1
    for (int s = 0; s < 4; s++) {
        __syncthreads();
        {   // stage pre-converted weights: pure float4 copies
            const float4* s0h = (const float4*)gW0hi[s];
            const float4* s0l = (const float4*)gW0lo[s];
            const float4* s1  = (const float4*)gW1t[s];
            const float4* s2  = (const float4*)gW2t[s];
            float4* d0h = (float4*)(sm + W0HI_OFF);
            float4* d0l = (float4*)(sm + W0LO_OFF);
            float4* d1  = (float4*)(sm + W1T_OFF);
            float4* d2  = (float4*)(sm + W2T_OFF);
            #pragma unroll 1
            for (int i = tid; i < 896; i += TPB) d0h[i] = s0h[i];
            #pragma unroll 1
            for (int i = tid; i < 896; i += TPB) d0l[i] = s0l[i];
            #pragma unroll 1
            for (int i = tid; i < 1024; i += TPB) d1[i] = s1[i];
            #pragma unroll 1
            for (int i = tid; i < 1024; i += TPB) d2[i] = s2[i];
            if (tid < 192) sm[BIAS_OFF + tid] = gBias[s][tid];
        }
        __syncthreads();

        const int srcoff = (s & 1) ? 64 : 0;
        const int tgtoff = 64 - srcoff;

        // ======== GEMM0: h = tanh(z_src @ W0^T + b0), compensated ==============
        {
            float acc[2][2][4];                 // [nn][mb][4]
            #pragma unroll
            for (int nn = 0; nn < 2; nn++)
                #pragma unroll
                for (int mb = 0; mb < 2; mb++)
                    #pragma unroll
                    for (int v = 0; v < 4; v++) acc[nn][mb][v] = 0.f;

            const int nlim = (warpQ == 3) ? 1 : 2;   // nt7 all-zero: skipped

            #pragma unroll
            for (int kt = 0; kt < 8; kt++) {
                const int kz = kt*8 + t;
                const int kc = srcoff + kz;
                uint32_t zh[2][4], zl[2][4];
                #pragma unroll
                for (int mb = 0; mb < 2; mb++) {
                    const int ra = rl + 16*mb, rb = ra + 8;
                    float v0 = ZM[ra*ZMSTR + kc];
                    float v1 = ZM[rb*ZMSTR + kc];
                    float v2 = ZM[ra*ZMSTR + kc+4];
                    float v3 = ZM[rb*ZMSTR + kc+4];
                    zh[mb][0] = __float_as_uint(v0) & 0xFFFFE000u;
                    zh[mb][1] = __float_as_uint(v1) & 0xFFFFE000u;
                    zh[mb][2] = __float_as_uint(v2) & 0xFFFFE000u;
                    zh[mb][3] = __float_as_uint(v3) & 0xFFFFE000u;
                    zl[mb][0] = __float_as_uint(v0 - __uint_as_float(zh[mb][0])) & 0xFFFFE000u;
                    zl[mb][1] = __float_as_uint(v1 - __uint_as_float(zh[mb][1])) & 0xFFFFE000u;
                    zl[mb][2] = __float_as_uint(v2 - __uint_as_float(zh[mb][2])) & 0xFFFFE000u;
                    zl[mb][3] = __float_as_uint(v3 - __uint_as_float(zh[mb][3])) & 0xFFFFE000u;
                }
                #pragma unroll
                for (int nn = 0; nn < 2; nn++) {
                    if (nn < nlim) {
                        const int n = (nt0 + nn)*8 + g;
                        const uint32_t bh0 = w0hiU[idx8(n, kz)];
                        const uint32_t bh1 = w0hiU[idx8(n, kz+4)];
                        const uint32_t bl0 = w0loU[idx8(n, kz)];
                        const uint32_t bl1 = w0loU[idx8(n, kz+4)];
                        #pragma unroll
                        for (int mb = 0; mb < 2; mb++) {
                            hmma(acc[nn][mb], zh[mb][0], zh[mb][1], zh[mb][2], zh[mb][3], bh0, bh1);
                            hmma(acc[nn][mb], zh[mb][0], zh[mb][1], zh[mb][2], zh[mb][3], bl0, bl1);
                            hmma(acc[nn][mb], zl[mb][0], zl[mb][1], zl[mb][2], zl[mb][3], bh0, bh1);
                        }
                    }
                }
            }
            // tanh epilogue -> H (tf32-rna); zero tiles for nt==7
            const int nlimE = (warpQ == 3) ? 1 : 2;
            #pragma unroll
            for (int nn = 0; nn < 2; nn++) {
                const int cb = (nt0 + nn)*8 + 2*t;
                #pragma unroll
                for (int mb = 0; mb < 2; mb++) {
                    const int ra = rl + 16*mb, rb = ra + 8;
                    if (nn >= nlimE) {
                        *(float2*)(H + idx8(ra, cb)) = make_float2(0.f, 0.f);
                        *(float2*)(H + idx8(rb, cb)) = make_float2(0.f, 0.f);
                    } else {
                        float h00 = tanha(acc[nn][mb][0] + b0sh[cb]);
                        float h01 = tanha(acc[nn][mb][1] + b0sh[cb+1]);
                        float h10 = tanha(acc[nn][mb][2] + b0sh[cb]);
                        float h11 = tanha(acc[nn][mb][3] + b0sh[cb+1]);
                        *(float2*)(H + idx8(ra, cb)) = make_float2(
                            __uint_as_float(tf32_rna_bits(h00)),
                            __uint_as_float(tf32_rna_bits(h01)));
                        *(float2*)(H + idx8(rb, cb)) = make_float2(
                            __uint_as_float(tf32_rna_bits(h10)),
                            __uint_as_float(tf32_rna_bits(h11)));
                    }
                }
            }
        }
        __syncthreads();   // H complete (cross-warp consumption next)

        // ======== GEMM1/2: mew, sr ; update target half + logdet ===============
        {
            float am2[2][2][4], av2[2][2][4];   // [nn][mb][4]
            #pragma unroll
            for (int nn = 0; nn < 2; nn++)
                #pragma unroll
                for (int mb = 0; mb < 2; mb++)
                    #pragma unroll
                    for (int v = 0; v < 4; v++) { am2[nn][mb][v] = 0.f; av2[nn][mb][v] = 0.f; }

            #pragma unroll
            for (int kt = 0; kt < 7; kt++) {      // k-tile 7 all-zero: skipped
                const int k0 = kt*8 + t;
                uint32_t hf[2][4];
                #pragma unroll
                for (int mb = 0; mb < 2; mb++) {
                    const int ra = rl + 16*mb, rb = ra + 8;
                    hf[mb][0] = hU[idx8(ra, k0)];
                    hf[mb][1] = hU[idx8(rb, k0)];
                    hf[mb][2] = hU[idx8(ra, k0+4)];
                    hf[mb][3] = hU[idx8(rb, k0+4)];
                }
                #pragma unroll
                for (int nn = 0; nn < 2; nn++) {
                    const int n = (nt0 + nn)*8 + g;
                    const uint32_t c1h0 = w1tU[idx8(n, k0)], c1h1 = w1tU[idx8(n, k0+4)];
                    const uint32_t c2h0 = w2tU[idx8(n, k0)], c2h1 = w2tU[idx8(n, k0+4)];
                    #pragma unroll
                    for (int mb = 0; mb < 2; mb++) {
                        hmma(am2[nn][mb], hf[mb][0], hf[mb][1], hf[mb][2], hf[mb][3], c1h0, c1h1);
                        hmma(av2[nn][mb], hf[mb][0], hf[mb][1], hf[mb][2], hf[mb][3], c2h0, c2h1);
                    }
                }
            }
            // update epilogue
            #pragma unroll
            for (int nn = 0; nn < 2; nn++) {
                const int cb = (nt0 + nn)*8 + 2*t;
                #pragma unroll
                for (int mb = 0; mb < 2; mb++) {
                    #pragma unroll
                    for (int hh = 0; hh < 2; hh++) {
                        const int r = rl + 16*mb + 8*hh;
                        const float mew0 = am2[nn][mb][2*hh+0] + b1sh[cb];
                        const float mew1 = am2[nn][mb][2*hh+1] + b1sh[cb+1];
                        const float sr0  = av2[nn][mb][2*hh+0] + b2sh[cb];
                        const float sr1  = av2[nn][mb][2*hh+1] + b2sh[cb+1];
                        const float e0 = __expf(-sr0), e1 = __expf(-sr1);
                        const float o0 = 1.f + e0,     o1 = 1.f + e1;
                        const float g0 = __fdividef(1.f, o0);
                        const float g1 = __fdividef(1.f, o1);
                        lgr[mb*2 + hh] += __log2f(o0) + __log2f(o1);
                        float2 zo = *(const float2*)(ZM + r*ZMSTR + tgtoff + cb);
                        const float zn0 = fmaf(zo.x, g0, mew0);
                        const float zn1 = fmaf(zo.y, g1, mew1);
                        *(float2*)(ZM + r*ZMSTR + tgtoff + cb) = make_float2(zn0, zn1);
                    }
                }
            }
        }
    }

    // ---------------- logdet reduce (lgpart unions dead H) ---------------------
    __syncthreads();
    #pragma unroll
    for (int i = 0; i < 4; i++) {
        float v = lgr[i];
        v += __shfl_xor_sync(0xFFFFFFFFu, v, 1);
        v += __shfl_xor_sync(0xFFFFFFFFu, v, 2);
        if (t == 0) {
            const int mb = i >> 1, hh = i & 1;
            lgpart[warpQ*128 + warpM*32 + 16*mb + 8*hh + g] = v;
        }
    }
    __syncthreads();

    // ---------------- epilogue: z_out + logpz ----------------------------------
    #pragma unroll 4
    for (int it = 0; it < 32; it++) {
        int j   = it*4 + (tid >> 7);
        int col = tid & 127;
        out[(r0 + j)*ZSv + col] = ZM[j*ZMSTR + col];
    }
    if (tid < 128) {
        float lg = lgpart[tid] + lgpart[128 + tid] + lgpart[256 + tid] + lgpart[384 + tid];
        float logq = -0.5f * ((float)ZSv * 1.8378770664093453f + rsum);
        out[(size_t)ROWS*ZSv + r0 + tid] = logq + 0.69314718055994531f * lg;
    }
}

extern "C" void kernel_launch(void* const* d_in, const int* in_sizes, int n_in,
                              void* d_out, int out_size) {
    (void)in_sizes; (void)n_in; (void)out_size;
    const float* mean   = (const float*)d_in[0];
    const float* logvar = (const float*)d_in[1];
    const float* eps    = (const float*)d_in[2];
    const float* W0     = (const float*)d_in[3];
    const float* b0     = (const float*)d_in[4];
    const float* W1     = (const float*)d_in[5];
    const float* b1     = (const float*)d_in[6];
    const float* W2     = (const float*)d_in[7];
    const float* b2     = (const float*)d_in[8];
    float* out = (float*)d_out;

    flow_prep<<<4, 256>>>(W0, b0, W1, b1, W2, b2);
    cudaFuncSetAttribute(flow_mma7, cudaFuncAttributeMaxDynamicSharedMemorySize, SMEM_BYTES);
    flow_mma7<<<NBLK, TPB, SMEM_BYTES>>>(mean, logvar, eps, out);
}

// round 13
// speedup vs baseline: 1.5778x; 1.0837x over previous
#include <cuda_runtime.h>
#include <cstdint>

// Flow1: K=32, B=4096, ZS=128, ZH=64, HS=50, NF=2
#define KK   32
#define BB   4096
#define ZSv  128
#define ZHv  64
#define HSv  50
#define ROWS (KK*BB)          // 131072
#define TPB  512              // 16 warps: 4 M-stripes (32 rows) x 4 N-quarters
#define MT   128              // rows per CTA
#define NBLK (ROWS/MT)        // 1024
#define ZMSTR 132             // z master stride

// smem float-index offsets
#define ZM_OFF   0                       // z master [128][132] fp32
#define H_OFF    (MT*ZMSTR)              // 16896: h tile (tf32-rna) [128][64]
#define W0F_OFF  (H_OFF + MT*64)         // 25088: W0 fragment-major [7][8][32][4]
#define W12F_OFF (W0F_OFF + 7168)        // 32256: W1/W2 fragment-major [8][7][32][4]
#define BIAS_OFF (W12F_OFF + 7168)       // 39424: b0[64] b1[64] b2[64]
#define SMEM_FLOATS (BIAS_OFF + 192)     // 39616
#define SMEM_BYTES  (SMEM_FLOATS * 4)    // 158464 -> 1 CTA/SM
#define RP_OFF   W0F_OFF                 // rowpart [128][4] (prologue only)
#define LG_OFF   H_OFF                   // lgpart [4][128] (epilogue only)

// pre-converted fragment-major weights (filled by prep kernel each launch)
__device__ __align__(16) float gW0f [4][7168];   // [nt0..6][kt0..7][lane][{hi_k,hi_k4,lo_k,lo_k4}]
__device__ __align__(16) float gW12f[4][7168];   // [nt0..7][kt0..6][lane][{w1_k,w1_k4,w2_k,w2_k4}]
__device__ __align__(16) float gBias[4][192];

__device__ __forceinline__ uint32_t tf32_rna_bits(float x) {
    uint32_t u; asm("cvt.rna.tf32.f32 %0, %1;" : "=r"(u) : "f"(x));
    return u;
}
__device__ __forceinline__ float truncm(float x) {
    return __uint_as_float(__float_as_uint(x) & 0xFFFFE000u);
}
__device__ __forceinline__ float tanha(float x) {
    float y; asm("tanh.approx.f32 %0, %1;" : "=f"(y) : "f"(x));
    return y;
}
__device__ __forceinline__ int idx8(int r, int c) {
    return r * 64 + (c ^ ((r & 7) << 2));
}
__device__ __forceinline__ void hmma(float (&d)[4],
                                     uint32_t a0, uint32_t a1, uint32_t a2, uint32_t a3,
                                     uint32_t b0, uint32_t b1) {
    asm volatile(
        "mma.sync.aligned.m16n8k8.row.col.f32.tf32.tf32.f32 "
        "{%0,%1,%2,%3}, {%4,%5,%6,%7}, {%8,%9}, {%0,%1,%2,%3};"
        : "+f"(d[0]), "+f"(d[1]), "+f"(d[2]), "+f"(d[3])
        : "r"(a0), "r"(a1), "r"(a2), "r"(a3), "r"(b0), "r"(b1));
}

// ---- prep: convert weights to fragment-major (4 CTAs, one per half-step) ----
__global__ void flow_prep(const float* __restrict__ W0, const float* __restrict__ b0,
                          const float* __restrict__ W1, const float* __restrict__ b1,
                          const float* __restrict__ W2, const float* __restrict__ b2)
{
    const int s = blockIdx.x;
    const int tid = threadIdx.x;
    const float* W0g = W0 + s*(HSv*ZHv);
    // GEMM0 fragments: i = (nt*8 + kt)*32 + lane
    for (int i = tid; i < 7*8*32; i += blockDim.x) {
        int lane = i & 31, ktn = i >> 5;
        int kt = ktn & 7, nt = ktn >> 3;
        int n  = nt*8 + (lane >> 2);
        int kz = kt*8 + (lane & 3);
        float v0 = (n < HSv) ? W0g[n*ZHv + kz]     : 0.f;
        float v1 = (n < HSv) ? W0g[n*ZHv + kz + 4] : 0.f;
        float h0 = truncm(v0), h1 = truncm(v1);
        gW0f[s][i*4+0] = h0;
        gW0f[s][i*4+1] = h1;
        gW0f[s][i*4+2] = __uint_as_float(tf32_rna_bits(v0 - h0));
        gW0f[s][i*4+3] = __uint_as_float(tf32_rna_bits(v1 - h1));
    }
    // GEMM1/2 fragments: i = (nt*7 + kt)*32 + lane
    const float* W1g = W1 + s*(ZHv*HSv);
    const float* W2g = W2 + s*(ZHv*HSv);
    for (int i = tid; i < 8*7*32; i += blockDim.x) {
        int lane = i & 31, ktn = i >> 5;
        int kt = ktn % 7, nt = ktn / 7;
        int n  = nt*8 + (lane >> 2);
        int k0 = kt*8 + (lane & 3);
        float a = (k0 < HSv)     ? W1g[n*HSv + k0]     : 0.f;
        float b = (k0 + 4 < HSv) ? W1g[n*HSv + k0 + 4] : 0.f;
        float c = (k0 < HSv)     ? W2g[n*HSv + k0]     : 0.f;
        float d = (k0 + 4 < HSv) ? W2g[n*HSv + k0 + 4] : 0.f;
        gW12f[s][i*4+0] = __uint_as_float(tf32_rna_bits(a));
        gW12f[s][i*4+1] = __uint_as_float(tf32_rna_bits(b));
        gW12f[s][i*4+2] = __uint_as_float(tf32_rna_bits(c));
        gW12f[s][i*4+3] = __uint_as_float(tf32_rna_bits(d));
    }
    if (tid < 64) {
        gBias[s][tid]       = (tid < HSv) ? b0[s*HSv + tid] : 0.f;
        gBias[s][64 + tid]  = b1[s*ZHv + tid];
        gBias[s][128 + tid] = b2[s*ZHv + tid];
    }
}

// ---- main flow kernel --------------------------------------------------------
__global__ void __launch_bounds__(TPB, 1) flow_mma8(
    const float* __restrict__ mean, const float* __restrict__ logvar,
    const float* __restrict__ eps, float* __restrict__ out)
{
    extern __shared__ float sm[];
    float* ZM    = sm + ZM_OFF;
    float* H     = sm + H_OFF;
    float* b0sh  = sm + BIAS_OFF;
    float* b1sh  = b0sh + 64;
    float* b2sh  = b1sh + 64;
    float* rowpart = sm + RP_OFF;
    float* lgpart  = sm + LG_OFF;

    const int tid   = threadIdx.x;
    const int lane  = tid & 31;
    const int warp  = tid >> 5;
    const int warpM = warp & 3;        // M stripe (32 rows, m32 per warp)
    const int warpQ = warp >> 2;       // N quarter (2 n-tiles)
    const int g     = lane >> 2;
    const int t     = lane & 3;
    const int rl    = warpM * 32 + g;  // m16 block rows: rl,rl+8 ; rl+16,rl+24
    const int nt0   = warpQ * 2;
    const size_t r0    = (size_t)blockIdx.x * MT;
    const size_t bbase = (size_t)(r0 & (BB-1)) * ZSv;

    // per-lane fragment-major weight pointers
    const float4* w0fp  = (const float4*)(sm + W0F_OFF)  + lane;
    const float4* w12fp = (const float4*)(sm + W12F_OFF) + lane;

    // ---------------- prologue: z = eps*exp(0.5*lv)+mean ; rowsum(lv+eps^2) ----
    #pragma unroll 4
    for (int it = 0; it < 32; it++) {
        int j   = it*4 + (tid >> 7);
        int col = tid & 127;
        size_t go = (size_t)j * ZSv + col;
        float ep = eps[r0*ZSv + go];
        float lv = logvar[bbase + go];
        float mn = mean[bbase + go];
        ZM[j*ZMSTR + col] = fmaf(ep, __expf(0.5f*lv), mn);
        float c = fmaf(ep, ep, lv);
        #pragma unroll
        for (int o = 16; o; o >>= 1) c += __shfl_xor_sync(0xFFFFFFFFu, c, o);
        if (lane == 0) rowpart[j*4 + ((tid >> 5) & 3)] = c;
    }
    __syncthreads();
    float rsum = 0.f;
    if (tid < 128)
        rsum = rowpart[tid*4+0] + rowpart[tid*4+1] + rowpart[tid*4+2] + rowpart[tid*4+3];

    float lgr[4] = {0.f, 0.f, 0.f, 0.f};   // [mb*2+hh]: rows rl+16mb+8hh

    const uint32_t* hU = (const uint32_t*)H;

    // ---------------- 4 flow half-steps ---------------------------------------
    #pragma unroll 1
    for (int s = 0; s < 4; s++) {
        __syncthreads();
        {   // stage pre-converted fragment-major weights: pure float4 copies
            const float4* s0  = (const float4*)gW0f[s];
            const float4* s12 = (const float4*)gW12f[s];
            float4* d0  = (float4*)(sm + W0F_OFF);
            float4* d12 = (float4*)(sm + W12F_OFF);
            #pragma unroll 1
            for (int i = tid; i < 1792; i += TPB) d0[i] = s0[i];
            #pragma unroll 1
            for (int i = tid; i < 1792; i += TPB) d12[i] = s12[i];
            if (tid < 192) sm[BIAS_OFF + tid] = gBias[s][tid];
        }
        __syncthreads();

        const int srcoff = (s & 1) ? 64 : 0;
        const int tgtoff = 64 - srcoff;

        // ======== GEMM0: h = tanh(z_src @ W0^T + b0); A = rna(z), W0 hi/lo =====
        {
            float acc[2][2][4];                 // [nn][mb][4]
            #pragma unroll
            for (int nn = 0; nn < 2; nn++)
                #pragma unroll
                for (int mb = 0; mb < 2; mb++)
                    #pragma unroll
                    for (int v = 0; v < 4; v++) acc[nn][mb][v] = 0.f;

            const int nlim = (warpQ == 3) ? 1 : 2;   // nt7 all-zero: skipped

            #pragma unroll
            for (int kt = 0; kt < 8; kt++) {
                const int kc = srcoff + kt*8 + t;
                uint32_t za[2][4];
                #pragma unroll
                for (int mb = 0; mb < 2; mb++) {
                    const int ra = rl + 16*mb, rb = ra + 8;
                    za[mb][0] = tf32_rna_bits(ZM[ra*ZMSTR + kc]);
                    za[mb][1] = tf32_rna_bits(ZM[rb*ZMSTR + kc]);
                    za[mb][2] = tf32_rna_bits(ZM[ra*ZMSTR + kc+4]);
                    za[mb][3] = tf32_rna_bits(ZM[rb*ZMSTR + kc+4]);
                }
                #pragma unroll
                for (int nn = 0; nn < 2; nn++) {
                    if (nn < nlim) {
                        const float4 w = w0fp[((nt0 + nn)*8 + kt)*32];
                        const uint32_t bh0 = __float_as_uint(w.x);
                        const uint32_t bh1 = __float_as_uint(w.y);
                        const uint32_t bl0 = __float_as_uint(w.z);
                        const uint32_t bl1 = __float_as_uint(w.w);
                        #pragma unroll
                        for (int mb = 0; mb < 2; mb++) {
                            hmma(acc[nn][mb], za[mb][0], za[mb][1], za[mb][2], za[mb][3], bh0, bh1);
                            hmma(acc[nn][mb], za[mb][0], za[mb][1], za[mb][2], za[mb][3], bl0, bl1);
                        }
                    }
                }
            }
            // tanh epilogue -> H (tf32-rna); zero tiles for nt==7
            const int nlimE = (warpQ == 3) ? 1 : 2;
            #pragma unroll
            for (int nn = 0; nn < 2; nn++) {
                const int cb = (nt0 + nn)*8 + 2*t;
                #pragma unroll
                for (int mb = 0; mb < 2; mb++) {
                    const int ra = rl + 16*mb, rb = ra + 8;
                    if (nn >= nlimE) {
                        *(float2*)(H + idx8(ra, cb)) = make_float2(0.f, 0.f);
                        *(float2*)(H + idx8(rb, cb)) = make_float2(0.f, 0.f);
                    } else {
                        float h00 = tanha(acc[nn][mb][0] + b0sh[cb]);
                        float h01 = tanha(acc[nn][mb][1] + b0sh[cb+1]);
                        float h10 = tanha(acc[nn][mb][2] + b0sh[cb]);
                        float h11 = tanha(acc[nn][mb][3] + b0sh[cb+1]);
                        *(float2*)(H + idx8(ra, cb)) = make_float2(
                            __uint_as_float(tf32_rna_bits(h00)),
                            __uint_as_float(tf32_rna_bits(h01)));
                        *(float2*)(H + idx8(rb, cb)) = make_float2(
                            __uint_as_float(tf32_rna_bits(h10)),
                            __uint_as_float(tf32_rna_bits(h11)));
                    }
                }
            }
        }
        __syncthreads();   // H complete (cross-warp consumption next)

        // ======== GEMM1/2: mew, sr ; update target half + logdet ===============
        {
            float am2[2][2][4], av2[2][2][4];   // [nn][mb][4]
            #pragma unroll
            for (int nn = 0; nn < 2; nn++)
                #pragma unroll
                for (int mb = 0; mb < 2; mb++)
                    #pragma unroll
                    for (int v = 0; v < 4; v++) { am2[nn][mb][v] = 0.f; av2[nn][mb][v] = 0.f; }

            #pragma unroll
            for (int kt = 0; kt < 7; kt++) {      // k-tile 7 all-zero: skipped
                const int k0 = kt*8 + t;
                uint32_t hf[2][4];
                #pragma unroll
                for (int mb = 0; mb < 2; mb++) {
                    const int ra = rl + 16*mb, rb = ra + 8;
                    hf[mb][0] = hU[idx8(ra, k0)];
                    hf[mb][1] = hU[idx8(rb, k0)];
                    hf[mb][2] = hU[idx8(ra, k0+4)];
                    hf[mb][3] = hU[idx8(rb, k0+4)];
                }
                #pragma unroll
                for (int nn = 0; nn < 2; nn++) {
                    const float4 w = w12fp[((nt0 + nn)*7 + kt)*32];
                    const uint32_t c1h0 = __float_as_uint(w.x);
                    const uint32_t c1h1 = __float_as_uint(w.y);
                    const uint32_t c2h0 = __float_as_uint(w.z);
                    const uint32_t c2h1 = __float_as_uint(w.w);
                    #pragma unroll
                    for (int mb = 0; mb < 2; mb++) {
                        hmma(am2[nn][mb], hf[mb][0], hf[mb][1], hf[mb][2], hf[mb][3], c1h0, c1h1);
                        hmma(av2[nn][mb], hf[mb][0], hf[mb][1], hf[mb][2], hf[mb][3], c2h0, c2h1);
                    }
                }
            }
            // update epilogue
            #pragma unroll
            for (int nn = 0; nn < 2; nn++) {
                const int cb = (nt0 + nn)*8 + 2*t;
                #pragma unroll
                for (int mb = 0; mb < 2; mb++) {
                    #pragma unroll
                    for (int hh = 0; hh < 2; hh++) {
                        const int r = rl + 16*mb + 8*hh;
                        const float mew0 = am2[nn][mb][2*hh+0] + b1sh[cb];
                        const float mew1 = am2[nn][mb][2*hh+1] + b1sh[cb+1];
                        const float sr0  = av2[nn][mb][2*hh+0] + b2sh[cb];
                        const float sr1  = av2[nn][mb][2*hh+1] + b2sh[cb+1];
                        const float e0 = __expf(-sr0), e1 = __expf(-sr1);
                        const float o0 = 1.f + e0,     o1 = 1.f + e1;
                        const float g0 = __fdividef(1.f, o0);
                        const float g1 = __fdividef(1.f, o1);
                        lgr[mb*2 + hh] += __log2f(o0) + __log2f(o1);
                        float2 zo = *(const float2*)(ZM + r*ZMSTR + tgtoff + cb);
                        const float zn0 = fmaf(zo.x, g0, mew0);
                        const float zn1 = fmaf(zo.y, g1, mew1);
                        *(float2*)(ZM + r*ZMSTR + tgtoff + cb) = make_float2(zn0, zn1);
                    }
                }
            }
        }
    }

    // ---------------- logdet reduce (lgpart unions dead H) ---------------------
    __syncthreads();
    #pragma unroll
    for (int i = 0; i < 4; i++) {
        float v = lgr[i];
        v += __shfl_xor_sync(0xFFFFFFFFu, v, 1);
        v += __shfl_xor_sync(0xFFFFFFFFu, v, 2);
        if (t == 0) {
            const int mb = i >> 1, hh = i & 1;
            lgpart[warpQ*128 + warpM*32 + 16*mb + 8*hh + g] = v;
        }
    }
    __syncthreads();

    // ---------------- epilogue: z_out + logpz ----------------------------------
    #pragma unroll 4
    for (int it = 0; it < 32; it++) {
        int j   = it*4 + (tid >> 7);
        int col = tid & 127;
        out[(r0 + j)*ZSv + col] = ZM[j*ZMSTR + col];
    }
    if (tid < 128) {
        float lg = lgpart[tid] + lgpart[128 + tid] + lgpart[256 + tid] + lgpart[384 + tid];
        float logq = -0.5f * ((float)ZSv * 1.8378770664093453f + rsum);
        out[(size_t)ROWS*ZSv + r0 + tid] = logq + 0.69314718055994531f * lg;
    }
}

extern "C" void kernel_launch(void* const* d_in, const int* in_sizes, int n_in,
                              void* d_out, int out_size) {
    (void)in_sizes; (void)n_in; (void)out_size;
    const float* mean   = (const float*)d_in[0];
    const float* logvar = (const float*)d_in[1];
    const float* eps    = (const float*)d_in[2];
    const float* W0     = (const float*)d_in[3];
    const float* b0     = (const float*)d_in[4];
    const float* W1     = (const float*)d_in[5];
    const float* b1     = (const float*)d_in[6];
    const float* W2     = (const float*)d_in[7];
    const float* b2     = (const float*)d_in[8];
    float* out = (float*)d_out;

    flow_prep<<<4, 256>>>(W0, b0, W1, b1, W2, b2);
    cudaFuncSetAttribute(flow_mma8, cudaFuncAttributeMaxDynamicSharedMemorySize, SMEM_BYTES);
    flow_mma8<<<NBLK, TPB, SMEM_BYTES>>>(mean, logvar, eps, out);
}

// round 14
// speedup vs baseline: 1.8972x; 1.2024x over previous
#include <cuda_runtime.h>
#include <cstdint>

// Flow1: K=32, B=4096, ZS=128, ZH=64, HS=50, NF=2
#define KK   32
#define BB   4096
#define ZSv  128
#define ZHv  64
#define HSv  50
#define ROWS (KK*BB)          // 131072
#define TPB  256              // 8 warps: 4 M-stripes (16 rows) x 2 N-halves
#define MT   64               // rows per CTA
#define NBLK (ROWS/MT)        // 2048
#define ZMSTR 132             // z master stride

// smem float-index offsets
#define ZM_OFF   0                       // z master [64][132] fp32
#define H_OFF    (MT*ZMSTR)              // 8448: h tile (tf32-rna) [64][64]
#define BIAS_OFF (H_OFF + MT*64)         // 12544: all 4 steps' biases [4][192]
#define LG_OFF   (BIAS_OFF + 768)        // 13312: lgpart [2][64]
#define SMEM_FLOATS (LG_OFF + 128)       // 13440
#define SMEM_BYTES  (SMEM_FLOATS * 4)    // 53760 -> 2 CTAs/SM
#define RP_OFF   H_OFF                   // rowpart [64][4] (prologue only)

// pre-converted fragment-major weights (filled by prep kernel each launch)
__device__ __align__(16) float gW0f [4][3584];   // [nt0..6][kt0..7][lane][{rna_k,rna_k4}]
__device__ __align__(16) float gW12f[4][7168];   // [nt0..7][kt0..6][lane][{w1_k,w1_k4,w2_k,w2_k4}]
__device__ __align__(16) float gBias[4][192];

__device__ __forceinline__ uint32_t tf32_rna_bits(float x) {
    uint32_t u; asm("cvt.rna.tf32.f32 %0, %1;" : "=r"(u) : "f"(x));
    return u;
}
__device__ __forceinline__ float tanha(float x) {
    float y; asm("tanh.approx.f32 %0, %1;" : "=f"(y) : "f"(x));
    return y;
}
__device__ __forceinline__ int idx8(int r, int c) {
    return r * 64 + (c ^ ((r & 7) << 2));
}
__device__ __forceinline__ void hmma(float (&d)[4],
                                     uint32_t a0, uint32_t a1, uint32_t a2, uint32_t a3,
                                     uint32_t b0, uint32_t b1) {
    asm volatile(
        "mma.sync.aligned.m16n8k8.row.col.f32.tf32.tf32.f32 "
        "{%0,%1,%2,%3}, {%4,%5,%6,%7}, {%8,%9}, {%0,%1,%2,%3};"
        : "+f"(d[0]), "+f"(d[1]), "+f"(d[2]), "+f"(d[3])
        : "r"(a0), "r"(a1), "r"(a2), "r"(a3), "r"(b0), "r"(b1));
}

// ---- prep: convert weights to fragment-major (4 CTAs, one per half-step) ----
__global__ void flow_prep(const float* __restrict__ W0, const float* __restrict__ b0,
                          const float* __restrict__ W1, const float* __restrict__ b1,
                          const float* __restrict__ W2, const float* __restrict__ b2)
{
    const int s = blockIdx.x;
    const int tid = threadIdx.x;
    const float* W0g = W0 + s*(HSv*ZHv);
    // GEMM0 fragments (rna tf32): i = (nt*8 + kt)*32 + lane
    for (int i = tid; i < 7*8*32; i += blockDim.x) {
        int lane = i & 31, ktn = i >> 5;
        int kt = ktn & 7, nt = ktn >> 3;
        int n  = nt*8 + (lane >> 2);
        int kz = kt*8 + (lane & 3);
        float v0 = (n < HSv) ? W0g[n*ZHv + kz]     : 0.f;
        float v1 = (n < HSv) ? W0g[n*ZHv + kz + 4] : 0.f;
        gW0f[s][i*2+0] = __uint_as_float(tf32_rna_bits(v0));
        gW0f[s][i*2+1] = __uint_as_float(tf32_rna_bits(v1));
    }
    // GEMM1/2 fragments: i = (nt*7 + kt)*32 + lane
    const float* W1g = W1 + s*(ZHv*HSv);
    const float* W2g = W2 + s*(ZHv*HSv);
    for (int i = tid; i < 8*7*32; i += blockDim.x) {
        int lane = i & 31, ktn = i >> 5;
        int kt = ktn % 7, nt = ktn / 7;
        int n  = nt*8 + (lane >> 2);
        int k0 = kt*8 + (lane & 3);
        float a = (k0 < HSv)     ? W1g[n*HSv + k0]     : 0.f;
        float b = (k0 + 4 < HSv) ? W1g[n*HSv + k0 + 4] : 0.f;
        float c = (k0 < HSv)     ? W2g[n*HSv + k0]     : 0.f;
        float d = (k0 + 4 < HSv) ? W2g[n*HSv + k0 + 4] : 0.f;
        gW12f[s][i*4+0] = __uint_as_float(tf32_rna_bits(a));
        gW12f[s][i*4+1] = __uint_as_float(tf32_rna_bits(b));
        gW12f[s][i*4+2] = __uint_as_float(tf32_rna_bits(c));
        gW12f[s][i*4+3] = __uint_as_float(tf32_rna_bits(d));
    }
    if (tid < 64) {
        gBias[s][tid]       = (tid < HSv) ? b0[s*HSv + tid] : 0.f;
        gBias[s][64 + tid]  = b1[s*ZHv + tid];
        gBias[s][128 + tid] = b2[s*ZHv + tid];
    }
}

// ---- main flow kernel --------------------------------------------------------
__global__ void __launch_bounds__(TPB, 2) flow_mma9(
    const float* __restrict__ mean, const float* __restrict__ logvar,
    const float* __restrict__ eps, float* __restrict__ out)
{
    extern __shared__ float sm[];
    float* ZM      = sm + ZM_OFF;
    float* H       = sm + H_OFF;
    float* biasAll = sm + BIAS_OFF;
    float* lgpart  = sm + LG_OFF;
    float* rowpart = sm + RP_OFF;

    const int tid   = threadIdx.x;
    const int lane  = tid & 31;
    const int warp  = tid >> 5;
    const int warpM = warp & 3;        // M stripe (16 rows)
    const int warpQ = warp >> 2;       // N half (4 n-tiles)
    const int g     = lane >> 2;
    const int t     = lane & 3;
    const int rl    = warpM * 16 + g;  // fragment rows rl, rl+8
    const int nt0   = warpQ * 4;
    const size_t r0    = (size_t)blockIdx.x * MT;
    const size_t bbase = (size_t)(r0 & (BB-1)) * ZSv;

    // ---------------- prologue: bias stage + z init + rowsum -------------------
    for (int i = tid; i < 768; i += TPB)
        biasAll[i] = ((const float*)gBias)[i];

    #pragma unroll 4
    for (int it = 0; it < 32; it++) {
        int j   = it*2 + (tid >> 7);
        int col = tid & 127;
        size_t go = (size_t)j * ZSv + col;
        float ep = eps[r0*ZSv + go];
        float lv = logvar[bbase + go];
        float mn = mean[bbase + go];
        ZM[j*ZMSTR + col] = fmaf(ep, __expf(0.5f*lv), mn);
        float c = fmaf(ep, ep, lv);
        #pragma unroll
        for (int o = 16; o; o >>= 1) c += __shfl_xor_sync(0xFFFFFFFFu, c, o);
        if (lane == 0) rowpart[j*4 + ((tid >> 5) & 3)] = c;
    }
    __syncthreads();
    float rsum = 0.f;
    if (tid < 64)
        rsum = rowpart[tid*4+0] + rowpart[tid*4+1] + rowpart[tid*4+2] + rowpart[tid*4+3];
    __syncthreads();   // rowpart region (H) reused below

    float lgr[2] = {0.f, 0.f};   // rows rl, rl+8

    const uint32_t* hU = (const uint32_t*)H;

    // ---------------- 4 flow half-steps ---------------------------------------
    #pragma unroll 1
    for (int s = 0; s < 4; s++) {
        const float* b0sh = biasAll + s*192;
        const float* b1sh = b0sh + 64;
        const float* b2sh = b1sh + 64;
        const float2* w0fp  = (const float2*)gW0f[s]  + lane;
        const float4* w12fp = (const float4*)gW12f[s] + lane;

        const int srcoff = (s & 1) ? 64 : 0;
        const int tgtoff = 64 - srcoff;

        // ======== GEMM0: h = tanh(z_src @ W0^T + b0); A=rna(z), W0=rna ========
        {
            float acc[4][4];
            #pragma unroll
            for (int nn = 0; nn < 4; nn++)
                #pragma unroll
                for (int v = 0; v < 4; v++) acc[nn][v] = 0.f;

            const int nlim = (warpQ == 1) ? 3 : 4;   // nt7 all-zero: skipped

            #pragma unroll
            for (int kt = 0; kt < 8; kt++) {
                const int kc = srcoff + kt*8 + t;
                const int rb = rl + 8;
                uint32_t za0 = tf32_rna_bits(ZM[rl*ZMSTR + kc]);
                uint32_t za1 = tf32_rna_bits(ZM[rb*ZMSTR + kc]);
                uint32_t za2 = tf32_rna_bits(ZM[rl*ZMSTR + kc+4]);
                uint32_t za3 = tf32_rna_bits(ZM[rb*ZMSTR + kc+4]);
                #pragma unroll
                for (int nn = 0; nn < 4; nn++) {
                    if (nn < nlim) {
                        const float2 w = __ldg(&w0fp[((nt0 + nn)*8 + kt)*32]);
                        hmma(acc[nn], za0, za1, za2, za3,
                             __float_as_uint(w.x), __float_as_uint(w.y));
                    }
                }
            }
            // tanh epilogue -> H (tf32-rna); zero tiles for nt==7
            const int nlimE = (warpQ == 1) ? 3 : 4;
            #pragma unroll
            for (int nn = 0; nn < 4; nn++) {
                const int cb = (nt0 + nn)*8 + 2*t;
                const int rb = rl + 8;
                if (nn >= nlimE) {
                    *(float2*)(H + idx8(rl, cb)) = make_float2(0.f, 0.f);
                    *(float2*)(H + idx8(rb, cb)) = make_float2(0.f, 0.f);
                } else {
                    float h00 = tanha(acc[nn][0] + b0sh[cb]);
                    float h01 = tanha(acc[nn][1] + b0sh[cb+1]);
                    float h10 = tanha(acc[nn][2] + b0sh[cb]);
                    float h11 = tanha(acc[nn][3] + b0sh[cb+1]);
                    *(float2*)(H + idx8(rl, cb)) = make_float2(
                        __uint_as_float(tf32_rna_bits(h00)),
                        __uint_as_float(tf32_rna_bits(h01)));
                    *(float2*)(H + idx8(rb, cb)) = make_float2(
                        __uint_as_float(tf32_rna_bits(h10)),
                        __uint_as_float(tf32_rna_bits(h11)));
                }
            }
        }
        __syncthreads();   // H complete (cross-warp consumption next)

        // ======== GEMM1/2: mew, sr ; update target half + logdet ===============
        {
            float am2[4][4], av2[4][4];
            #pragma unroll
            for (int nn = 0; nn < 4; nn++)
                #pragma unroll
                for (int v = 0; v < 4; v++) { am2[nn][v] = 0.f; av2[nn][v] = 0.f; }

            #pragma unroll
            for (int kt = 0; kt < 7; kt++) {      // k-tile 7 all-zero: skipped
                const int k0 = kt*8 + t;
                const int rb = rl + 8;
                const uint32_t hf0 = hU[idx8(rl, k0)];
                const uint32_t hf1 = hU[idx8(rb, k0)];
                const uint32_t hf2 = hU[idx8(rl, k0+4)];
                const uint32_t hf3 = hU[idx8(rb, k0+4)];
                #pragma unroll
                for (int nn = 0; nn < 4; nn++) {
                    const float4 w = __ldg(&w12fp[((nt0 + nn)*7 + kt)*32]);
                    hmma(am2[nn], hf0, hf1, hf2, hf3,
                         __float_as_uint(w.x), __float_as_uint(w.y));
                    hmma(av2[nn], hf0, hf1, hf2, hf3,
                         __float_as_uint(w.z), __float_as_uint(w.w));
                }
            }
            // update epilogue
            #pragma unroll
            for (int nn = 0; nn < 4; nn++) {
                const int cb = (nt0 + nn)*8 + 2*t;
                #pragma unroll
                for (int hh = 0; hh < 2; hh++) {
                    const int r = rl + 8*hh;
                    const float mew0 = am2[nn][2*hh+0] + b1sh[cb];
                    const float mew1 = am2[nn][2*hh+1] + b1sh[cb+1];
                    const float sr0  = av2[nn][2*hh+0] + b2sh[cb];
                    const float sr1  = av2[nn][2*hh+1] + b2sh[cb+1];
                    const float e0 = __expf(-sr0), e1 = __expf(-sr1);
                    const float o0 = 1.f + e0,     o1 = 1.f + e1;
                    const float g0 = __fdividef(1.f, o0);
                    const float g1 = __fdividef(1.f, o1);
                    lgr[hh] += __log2f(o0) + __log2f(o1);
                    float2 zo = *(const float2*)(ZM + r*ZMSTR + tgtoff + cb);
                    const float zn0 = fmaf(zo.x, g0, mew0);
                    const float zn1 = fmaf(zo.y, g1, mew1);
                    *(float2*)(ZM + r*ZMSTR + tgtoff + cb) = make_float2(zn0, zn1);
                }
            }
        }
        __syncthreads();   // ZM updated before next step's GEMM0 / final output
    }

    // ---------------- logdet reduce ---------------------------------------------
    #pragma unroll
    for (int i = 0; i < 2; i++) {
        float v = lgr[i];
        v += __shfl_xor_sync(0xFFFFFFFFu, v, 1);
        v += __shfl_xor_sync(0xFFFFFFFFu, v, 2);
        if (t == 0)
            lgpart[warpQ*64 + warpM*16 + i*8 + g] = v;
    }
    __syncthreads();

    // ---------------- epilogue: z_out + logpz ----------------------------------
    #pragma unroll 4
    for (int it = 0; it < 32; it++) {
        int j   = it*2 + (tid >> 7);
        int col = tid & 127;
        out[(r0 + j)*ZSv + col] = ZM[j*ZMSTR + col];
    }
    if (tid < 64) {
        float lg = lgpart[tid] + lgpart[64 + tid];
        float logq = -0.5f * ((float)ZSv * 1.8378770664093453f + rsum);
        out[(size_t)ROWS*ZSv + r0 + tid] = logq + 0.69314718055994531f * lg;
    }
}

extern "C" void kernel_launch(void* const* d_in, const int* in_sizes, int n_in,
                              void* d_out, int out_size) {
    (void)in_sizes; (void)n_in; (void)out_size;
    const float* mean   = (const float*)d_in[0];
    const float* logvar = (const float*)d_in[1];
    const float* eps    = (const float*)d_in[2];
    const float* W0     = (const float*)d_in[3];
    const float* b0     = (const float*)d_in[4];
    const float* W1     = (const float*)d_in[5];
    const float* b1     = (const float*)d_in[6];
    const float* W2     = (const float*)d_in[7];
    const float* b2     = (const float*)d_in[8];
    float* out = (float*)d_out;

    flow_prep<<<4, 256>>>(W0, b0, W1, b1, W2, b2);
    cudaFuncSetAttribute(flow_mma9, cudaFuncAttributeMaxDynamicSharedMemorySize, SMEM_BYTES);
    flow_mma9<<<NBLK, TPB, SMEM_BYTES>>>(mean, logvar, eps, out);
}

// round 15
// speedup vs baseline: 2.1219x; 1.1185x over previous
#include <cuda_runtime.h>
#include <cstdint>

// Flow1: K=32, B=4096, ZS=128, ZH=64, HS=50, NF=2
#define KK   32
#define BB   4096
#define ZSv  128
#define ZHv  64
#define HSv  50
#define ROWS (KK*BB)          // 131072
#define TPB  256              // 8 warps: 4 M-stripes (32 rows) x 2 N-halves
#define MT   128              // rows per CTA
#define NBLK (ROWS/MT)        // 1024
#define ZMSTR 132             // z master stride

// smem float-index offsets
#define ZM_OFF   0                       // z master [128][132] fp32
#define H_OFF    (MT*ZMSTR)              // 16896: h tile (tf32-rna) [128][64]
#define BIAS_OFF (H_OFF + MT*64)         // 25088: all 4 steps' biases [4][192]
#define LG_OFF   (BIAS_OFF + 768)        // 25856: lgpart [2][128]
#define SMEM_FLOATS (LG_OFF + 256)       // 26112
#define SMEM_BYTES  (SMEM_FLOATS * 4)    // 104448 -> 2 CTAs/SM
#define RP_OFF   H_OFF                   // rowpart [128][4] (prologue only)

// pre-converted fragment-major weights (filled by prep kernel each launch)
__device__ __align__(16) float gW0f [4][3584];   // [nt0..6][kt0..7][lane][{rna_k,rna_k4}]
__device__ __align__(16) float gW12f[4][7168];   // [nt0..7][kt0..6][lane][{w1_k,w1_k4,w2_k,w2_k4}]
__device__ __align__(16) float gBias[4][192];

__device__ __forceinline__ uint32_t tf32_rna_bits(float x) {
    uint32_t u; asm("cvt.rna.tf32.f32 %0, %1;" : "=r"(u) : "f"(x));
    return u;
}
__device__ __forceinline__ float tanha(float x) {
    float y; asm("tanh.approx.f32 %0, %1;" : "=f"(y) : "f"(x));
    return y;
}
__device__ __forceinline__ int idx8(int r, int c) {
    return r * 64 + (c ^ ((r & 7) << 2));
}
__device__ __forceinline__ void hmma(float (&d)[4],
                                     uint32_t a0, uint32_t a1, uint32_t a2, uint32_t a3,
                                     uint32_t b0, uint32_t b1) {
    asm volatile(
        "mma.sync.aligned.m16n8k8.row.col.f32.tf32.tf32.f32 "
        "{%0,%1,%2,%3}, {%4,%5,%6,%7}, {%8,%9}, {%0,%1,%2,%3};"
        : "+f"(d[0]), "+f"(d[1]), "+f"(d[2]), "+f"(d[3])
        : "r"(a0), "r"(a1), "r"(a2), "r"(a3), "r"(b0), "r"(b1));
}

// ---- prep: convert weights to fragment-major (4 CTAs, one per half-step) ----
__global__ void flow_prep(const float* __restrict__ W0, const float* __restrict__ b0,
                          const float* __restrict__ W1, const float* __restrict__ b1,
                          const float* __restrict__ W2, const float* __restrict__ b2)
{
    const int s = blockIdx.x;
    const int tid = threadIdx.x;
    const float* W0g = W0 + s*(HSv*ZHv);
    // GEMM0 fragments (rna tf32): i = (nt*8 + kt)*32 + lane
    for (int i = tid; i < 7*8*32; i += blockDim.x) {
        int lane = i & 31, ktn = i >> 5;
        int kt = ktn & 7, nt = ktn >> 3;
        int n  = nt*8 + (lane >> 2);
        int kz = kt*8 + (lane & 3);
        float v0 = (n < HSv) ? W0g[n*ZHv + kz]     : 0.f;
        float v1 = (n < HSv) ? W0g[n*ZHv + kz + 4] : 0.f;
        gW0f[s][i*2+0] = __uint_as_float(tf32_rna_bits(v0));
        gW0f[s][i*2+1] = __uint_as_float(tf32_rna_bits(v1));
    }
    // GEMM1/2 fragments: i = (nt*7 + kt)*32 + lane
    const float* W1g = W1 + s*(ZHv*HSv);
    const float* W2g = W2 + s*(ZHv*HSv);
    for (int i = tid; i < 8*7*32; i += blockDim.x) {
        int lane = i & 31, ktn = i >> 5;
        int kt = ktn % 7, nt = ktn / 7;
        int n  = nt*8 + (lane >> 2);
        int k0 = kt*8 + (lane & 3);
        float a = (k0 < HSv)     ? W1g[n*HSv + k0]     : 0.f;
        float b = (k0 + 4 < HSv) ? W1g[n*HSv + k0 + 4] : 0.f;
        float c = (k0 < HSv)     ? W2g[n*HSv + k0]     : 0.f;
        float d = (k0 + 4 < HSv) ? W2g[n*HSv + k0 + 4] : 0.f;
        gW12f[s][i*4+0] = __uint_as_float(tf32_rna_bits(a));
        gW12f[s][i*4+1] = __uint_as_float(tf32_rna_bits(b));
        gW12f[s][i*4+2] = __uint_as_float(tf32_rna_bits(c));
        gW12f[s][i*4+3] = __uint_as_float(tf32_rna_bits(d));
    }
    if (tid < 64) {
        gBias[s][tid]       = (tid < HSv) ? b0[s*HSv + tid] : 0.f;
        gBias[s][64 + tid]  = b1[s*ZHv + tid];
        gBias[s][128 + tid] = b2[s*ZHv + tid];
    }
}

// ---- main flow kernel --------------------------------------------------------
__global__ void __launch_bounds__(TPB, 2) flow_mma10(
    const float* __restrict__ mean, const float* __restrict__ logvar,
    const float* __restrict__ eps, float* __restrict__ out)
{
    extern __shared__ float sm[];
    float* ZM      = sm + ZM_OFF;
    float* H       = sm + H_OFF;
    float* biasAll = sm + BIAS_OFF;
    float* lgpart  = sm + LG_OFF;
    float* rowpart = sm + RP_OFF;

    const int tid   = threadIdx.x;
    const int lane  = tid & 31;
    const int warp  = tid >> 5;
    const int warpM = warp & 3;        // M stripe (32 rows, m32 per warp)
    const int warpQ = warp >> 2;       // N half (4 n-tiles)
    const int g     = lane >> 2;
    const int t     = lane & 3;
    const int rl    = warpM * 32 + g;  // m16 blocks at rl(+8) and rl+16(+24)
    const int nt0   = warpQ * 4;
    const size_t r0    = (size_t)blockIdx.x * MT;
    const size_t bbase = (size_t)(r0 & (BB-1)) * ZSv;

    // ---------------- prologue: bias stage + z init + rowsum -------------------
    for (int i = tid; i < 768; i += TPB)
        biasAll[i] = ((const float*)gBias)[i];

    #pragma unroll 4
    for (int it = 0; it < 64; it++) {
        int j   = it*2 + (tid >> 7);
        int col = tid & 127;
        size_t go = (size_t)j * ZSv + col;
        float ep = eps[r0*ZSv + go];
        float lv = logvar[bbase + go];
        float mn = mean[bbase + go];
        ZM[j*ZMSTR + col] = fmaf(ep, __expf(0.5f*lv), mn);
        float c = fmaf(ep, ep, lv);
        #pragma unroll
        for (int o = 16; o; o >>= 1) c += __shfl_xor_sync(0xFFFFFFFFu, c, o);
        if (lane == 0) rowpart[j*4 + ((tid >> 5) & 3)] = c;
    }
    __syncthreads();
    float rsum = 0.f;
    if (tid < 128)
        rsum = rowpart[tid*4+0] + rowpart[tid*4+1] + rowpart[tid*4+2] + rowpart[tid*4+3];
    __syncthreads();   // rowpart region (H) reused below

    float lgr[4] = {0.f, 0.f, 0.f, 0.f};   // [mb*2+hh]: rows rl+16mb+8hh

    const uint32_t* hU = (const uint32_t*)H;

    // ---------------- 4 flow half-steps ---------------------------------------
    #pragma unroll 1
    for (int s = 0; s < 4; s++) {
        const float* b0sh = biasAll + s*192;
        const float* b1sh = b0sh + 64;
        const float* b2sh = b1sh + 64;
        const float2* w0fp  = (const float2*)gW0f[s]  + lane;
        const float4* w12fp = (const float4*)gW12f[s] + lane;

        const int srcoff = (s & 1) ? 64 : 0;
        const int tgtoff = 64 - srcoff;

        // ======== GEMM0: h = tanh(z_src @ W0^T + b0); A=rna(z), W0=rna ========
        {
            float acc[4][2][4];                 // [nn][mb][4]
            #pragma unroll
            for (int nn = 0; nn < 4; nn++)
                #pragma unroll
                for (int mb = 0; mb < 2; mb++)
                    #pragma unroll
                    for (int v = 0; v < 4; v++) acc[nn][mb][v] = 0.f;

            const int nlim = (warpQ == 1) ? 3 : 4;   // nt7 all-zero: skipped

            #pragma unroll
            for (int kt = 0; kt < 8; kt++) {
                const int kc = srcoff + kt*8 + t;
                uint32_t za[2][4];
                #pragma unroll
                for (int mb = 0; mb < 2; mb++) {
                    const int ra = rl + 16*mb, rb = ra + 8;
                    za[mb][0] = tf32_rna_bits(ZM[ra*ZMSTR + kc]);
                    za[mb][1] = tf32_rna_bits(ZM[rb*ZMSTR + kc]);
                    za[mb][2] = tf32_rna_bits(ZM[ra*ZMSTR + kc+4]);
                    za[mb][3] = tf32_rna_bits(ZM[rb*ZMSTR + kc+4]);
                }
                #pragma unroll
                for (int nn = 0; nn < 4; nn++) {
                    if (nn < nlim) {
                        const float2 w = __ldg(&w0fp[((nt0 + nn)*8 + kt)*32]);
                        const uint32_t b0w = __float_as_uint(w.x);
                        const uint32_t b1w = __float_as_uint(w.y);
                        #pragma unroll
                        for (int mb = 0; mb < 2; mb++)
                            hmma(acc[nn][mb], za[mb][0], za[mb][1], za[mb][2], za[mb][3],
                                 b0w, b1w);
                    }
                }
            }
            // tanh epilogue -> H (tf32-rna); zero tiles for nt==7
            const int nlimE = (warpQ == 1) ? 3 : 4;
            #pragma unroll
            for (int nn = 0; nn < 4; nn++) {
                const int cb = (nt0 + nn)*8 + 2*t;
                #pragma unroll
                for (int mb = 0; mb < 2; mb++) {
                    const int ra = rl + 16*mb, rb = ra + 8;
                    if (nn >= nlimE) {
                        *(float2*)(H + idx8(ra, cb)) = make_float2(0.f, 0.f);
                        *(float2*)(H + idx8(rb, cb)) = make_float2(0.f, 0.f);
                    } else {
                        float h00 = tanha(acc[nn][mb][0] + b0sh[cb]);
                        float h01 = tanha(acc[nn][mb][1] + b0sh[cb+1]);
                        float h10 = tanha(acc[nn][mb][2] + b0sh[cb]);
                        float h11 = tanha(acc[nn][mb][3] + b0sh[cb+1]);
                        *(float2*)(H + idx8(ra, cb)) = make_float2(
                            __uint_as_float(tf32_rna_bits(h00)),
                            __uint_as_float(tf32_rna_bits(h01)));
                        *(float2*)(H + idx8(rb, cb)) = make_float2(
                            __uint_as_float(tf32_rna_bits(h10)),
                            __uint_as_float(tf32_rna_bits(h11)));
                    }
                }
            }
        }
        __syncthreads();   // H complete (cross-warp consumption next)

        // ======== GEMM1/2: mew, sr ; update target half + logdet ===============
        #pragma unroll
        for (int grp = 0; grp < 2; grp++) {
            const int ntg = nt0 + grp*2;
            float am2[2][2][4], av2[2][2][4];   // [nn][mb][4]
            #pragma unroll
            for (int nn = 0; nn < 2; nn++)
                #pragma unroll
                for (int mb = 0; mb < 2; mb++)
                    #pragma unroll
                    for (int v = 0; v < 4; v++) { am2[nn][mb][v] = 0.f; av2[nn][mb][v] = 0.f; }

            #pragma unroll
            for (int kt = 0; kt < 7; kt++) {      // k-tile 7 all-zero: skipped
                const int k0 = kt*8 + t;
                uint32_t hf[2][4];
                #pragma unroll
                for (int mb = 0; mb < 2; mb++) {
                    const int ra = rl + 16*mb, rb = ra + 8;
                    hf[mb][0] = hU[idx8(ra, k0)];
                    hf[mb][1] = hU[idx8(rb, k0)];
                    hf[mb][2] = hU[idx8(ra, k0+4)];
                    hf[mb][3] = hU[idx8(rb, k0+4)];
                }
                #pragma unroll
                for (int nn = 0; nn < 2; nn++) {
                    const float4 w = __ldg(&w12fp[((ntg + nn)*7 + kt)*32]);
                    const uint32_t c1h0 = __float_as_uint(w.x);
                    const uint32_t c1h1 = __float_as_uint(w.y);
                    const uint32_t c2h0 = __float_as_uint(w.z);
                    const uint32_t c2h1 = __float_as_uint(w.w);
                    #pragma unroll
                    for (int mb = 0; mb < 2; mb++) {
                        hmma(am2[nn][mb], hf[mb][0], hf[mb][1], hf[mb][2], hf[mb][3], c1h0, c1h1);
                        hmma(av2[nn][mb], hf[mb][0], hf[mb][1], hf[mb][2], hf[mb][3], c2h0, c2h1);
                    }
                }
            }
            // update epilogue
            #pragma unroll
            for (int nn = 0; nn < 2; nn++) {
                const int cb = (ntg + nn)*8 + 2*t;
                #pragma unroll
                for (int mb = 0; mb < 2; mb++) {
                    #pragma unroll
                    for (int hh = 0; hh < 2; hh++) {
                        const int r = rl + 16*mb + 8*hh;
                        const float mew0 = am2[nn][mb][2*hh+0] + b1sh[cb];
                        const float mew1 = am2[nn][mb][2*hh+1] + b1sh[cb+1];
                        const float sr0  = av2[nn][mb][2*hh+0] + b2sh[cb];
                        const float sr1  = av2[nn][mb][2*hh+1] + b2sh[cb+1];
                        const float e0 = __expf(-sr0), e1 = __expf(-sr1);
                        const float o0 = 1.f + e0,     o1 = 1.f + e1;
                        const float g0 = __fdividef(1.f, o0);
                        const float g1 = __fdividef(1.f, o1);
                        lgr[mb*2 + hh] += __log2f(o0) + __log2f(o1);
                        float2 zo = *(const float2*)(ZM + r*ZMSTR + tgtoff + cb);
                        const float zn0 = fmaf(zo.x, g0, mew0);
                        const float zn1 = fmaf(zo.y, g1, mew1);
                        *(float2*)(ZM + r*ZMSTR + tgtoff + cb) = make_float2(zn0, zn1);
                    }
                }
            }
        }
        __syncthreads();   // ZM updated before next step's GEMM0 / final output
    }

    // ---------------- logdet reduce ---------------------------------------------
    #pragma unroll
    for (int i = 0; i < 4; i++) {
        float v = lgr[i];
        v += __shfl_xor_sync(0xFFFFFFFFu, v, 1);
        v += __shfl_xor_sync(0xFFFFFFFFu, v, 2);
        if (t == 0) {
            const int mb = i >> 1, hh = i & 1;
            lgpart[warpQ*128 + warpM*32 + 16*mb + 8*hh + g] = v;
        }
    }
    __syncthreads();

    // ---------------- epilogue: z_out + logpz ----------------------------------
    #pragma unroll 4
    for (int it = 0; it < 64; it++) {
        int j   = it*2 + (tid >> 7);
        int col = tid & 127;
        out[(r0 + j)*ZSv + col] = ZM[j*ZMSTR + col];
    }
    if (tid < 128) {
        float lg = lgpart[tid] + lgpart[128 + tid];
        float logq = -0.5f * ((float)ZSv * 1.8378770664093453f + rsum);
        out[(size_t)ROWS*ZSv + r0 + tid] = logq + 0.69314718055994531f * lg;
    }
}

extern "C" void kernel_launch(void* const* d_in, const int* in_sizes, int n_in,
                              void* d_out, int out_size) {
    (void)in_sizes; (void)n_in; (void)out_size;
    const float* mean   = (const float*)d_in[0];
    const float* logvar = (const float*)d_in[1];
    const float* eps    = (const float*)d_in[2];
    const float* W0     = (const float*)d_in[3];
    const float* b0     = (const float*)d_in[4];
    const float* W1     = (const float*)d_in[5];
    const float* b1     = (const float*)d_in[6];
    const float* W2     = (const float*)d_in[7];
    const float* b2     = (const float*)d_in[8];
    float* out = (float*)d_out;

    flow_prep<<<4, 256>>>(W0, b0, W1, b1, W2, b2);
    cudaFuncSetAttribute(flow_mma10, cudaFuncAttributeMaxDynamicSharedMemorySize, SMEM_BYTES);
    flow_mma10<<<NBLK, TPB, SMEM_BYTES>>>(mean, logvar, eps, out);
}

// round 16
// speedup vs baseline: 2.2038x; 1.0386x over previous
#include <cuda_runtime.h>
#include <cstdint>

// Flow1: K=32, B=4096, ZS=128, ZH=64, HS=50, NF=2
#define KK   32
#define BB   4096
#define ZSv  128
#define ZHv  64
#define HSv  50
#define ROWS (KK*BB)          // 131072
#define TPB  256              // 8 warps: 4 M-stripes (32 rows) x 2 N-halves
#define MT   128              // rows per CTA
#define NBLK (ROWS/MT)        // 1024
#define ZMSTR 132             // z master stride

// smem float-index offsets
#define ZM_OFF   0                       // z master [128][132] fp32
#define H_OFF    (MT*ZMSTR)              // 16896: h tile (tf32-rna) [128][64]
#define BIAS_OFF (H_OFF + MT*64)         // 25088: all 4 steps' biases [4][192]
#define LG_OFF   (BIAS_OFF + 768)        // 25856: lgpart [2][128]
#define SMEM_FLOATS (LG_OFF + 256)       // 26112
#define SMEM_BYTES  (SMEM_FLOATS * 4)    // 104448 -> 2 CTAs/SM
#define RP_OFF   H_OFF                   // rowpart [128][4] (prologue only)

// pre-converted fragment-major weights (filled by prep kernel each launch)
__device__ __align__(16) float gW0f [4][3584];   // [nt0..6][kt0..7][lane][{rna_k,rna_k4}]
__device__ __align__(16) float gW12f[4][7168];   // [nt0..7][kt0..6][lane][{w1_k,w1_k4,w2_k,w2_k4}]
__device__ __align__(16) float gBias[4][192];

__device__ __forceinline__ uint32_t tf32_rna_bits(float x) {
    uint32_t u; asm("cvt.rna.tf32.f32 %0, %1;" : "=r"(u) : "f"(x));
    return u;
}
__device__ __forceinline__ float tanha(float x) {
    float y; asm("tanh.approx.f32 %0, %1;" : "=f"(y) : "f"(x));
    return y;
}
__device__ __forceinline__ int idx8(int r, int c) {
    return r * 64 + (c ^ ((r & 7) << 2));
}
__device__ __forceinline__ void hmma(float (&d)[4],
                                     uint32_t a0, uint32_t a1, uint32_t a2, uint32_t a3,
                                     uint32_t b0, uint32_t b1) {
    asm volatile(
        "mma.sync.aligned.m16n8k8.row.col.f32.tf32.tf32.f32 "
        "{%0,%1,%2,%3}, {%4,%5,%6,%7}, {%8,%9}, {%0,%1,%2,%3};"
        : "+f"(d[0]), "+f"(d[1]), "+f"(d[2]), "+f"(d[3])
        : "r"(a0), "r"(a1), "r"(a2), "r"(a3), "r"(b0), "r"(b1));
}

// ---- prep: convert weights to fragment-major (4 CTAs, one per half-step) ----
__global__ void flow_prep(const float* __restrict__ W0, const float* __restrict__ b0,
                          const float* __restrict__ W1, const float* __restrict__ b1,
                          const float* __restrict__ W2, const float* __restrict__ b2)
{
    const int s = blockIdx.x;
    const int tid = threadIdx.x;
    const float* W0g = W0 + s*(HSv*ZHv);
    // GEMM0 fragments (rna tf32): i = (nt*8 + kt)*32 + lane
    for (int i = tid; i < 7*8*32; i += blockDim.x) {
        int lane = i & 31, ktn = i >> 5;
        int kt = ktn & 7, nt = ktn >> 3;
        int n  = nt*8 + (lane >> 2);
        int kz = kt*8 + (lane & 3);
        float v0 = (n < HSv) ? W0g[n*ZHv + kz]     : 0.f;
        float v1 = (n < HSv) ? W0g[n*ZHv + kz + 4] : 0.f;
        gW0f[s][i*2+0] = __uint_as_float(tf32_rna_bits(v0));
        gW0f[s][i*2+1] = __uint_as_float(tf32_rna_bits(v1));
    }
    // GEMM1/2 fragments: i = (nt*7 + kt)*32 + lane
    const float* W1g = W1 + s*(ZHv*HSv);
    const float* W2g = W2 + s*(ZHv*HSv);
    for (int i = tid; i < 8*7*32; i += blockDim.x) {
        int lane = i & 31, ktn = i >> 5;
        int kt = ktn % 7, nt = ktn / 7;
        int n  = nt*8 + (lane >> 2);
        int k0 = kt*8 + (lane & 3);
        float a = (k0 < HSv)     ? W1g[n*HSv + k0]     : 0.f;
        float b = (k0 + 4 < HSv) ? W1g[n*HSv + k0 + 4] : 0.f;
        float c = (k0 < HSv)     ? W2g[n*HSv + k0]     : 0.f;
        float d = (k0 + 4 < HSv) ? W2g[n*HSv + k0 + 4] : 0.f;
        gW12f[s][i*4+0] = __uint_as_float(tf32_rna_bits(a));
        gW12f[s][i*4+1] = __uint_as_float(tf32_rna_bits(b));
        gW12f[s][i*4+2] = __uint_as_float(tf32_rna_bits(c));
        gW12f[s][i*4+3] = __uint_as_float(tf32_rna_bits(d));
    }
    if (tid < 64) {
        gBias[s][tid]       = (tid < HSv) ? b0[s*HSv + tid] : 0.f;
        gBias[s][64 + tid]  = b1[s*ZHv + tid];
        gBias[s][128 + tid] = b2[s*ZHv + tid];
    }
}

// ---- main flow kernel --------------------------------------------------------
__global__ void __launch_bounds__(TPB, 2) flow_mma11(
    const float* __restrict__ mean, const float* __restrict__ logvar,
    const float* __restrict__ eps, float* __restrict__ out)
{
    extern __shared__ float sm[];
    float* ZM      = sm + ZM_OFF;
    float* H       = sm + H_OFF;
    float* biasAll = sm + BIAS_OFF;
    float* lgpart  = sm + LG_OFF;
    float* rowpart = sm + RP_OFF;

    const int tid   = threadIdx.x;
    const int lane  = tid & 31;
    const int warp  = tid >> 5;
    const int warpM = warp & 3;        // M stripe (32 rows, m32 per warp)
    const int warpQ = warp >> 2;       // N half (4 n-tiles)
    const int g     = lane >> 2;
    const int t     = lane & 3;
    const int rl    = warpM * 32 + g;  // m16 blocks at rl(+8) and rl+16(+24)
    const int nt0   = warpQ * 4;
    const size_t r0    = (size_t)blockIdx.x * MT;
    const size_t bbase = (size_t)(r0 & (BB-1)) * ZSv;

    // ---------------- prologue: bias stage + z init + rowsum -------------------
    for (int i = tid; i < 768; i += TPB)
        biasAll[i] = ((const float*)gBias)[i];

    #pragma unroll 4
    for (int it = 0; it < 64; it++) {
        int j   = it*2 + (tid >> 7);
        int col = tid & 127;
        size_t go = (size_t)j * ZSv + col;
        float ep = eps[r0*ZSv + go];
        float lv = logvar[bbase + go];
        float mn = mean[bbase + go];
        ZM[j*ZMSTR + col] = fmaf(ep, __expf(0.5f*lv), mn);
        float c = fmaf(ep, ep, lv);
        #pragma unroll
        for (int o = 16; o; o >>= 1) c += __shfl_xor_sync(0xFFFFFFFFu, c, o);
        if (lane == 0) rowpart[j*4 + ((tid >> 5) & 3)] = c;
    }
    __syncthreads();
    float rsum = 0.f;
    if (tid < 128)
        rsum = rowpart[tid*4+0] + rowpart[tid*4+1] + rowpart[tid*4+2] + rowpart[tid*4+3];
    __syncthreads();   // rowpart region (H) reused below

    float lgr[4] = {0.f, 0.f, 0.f, 0.f};   // [mb*2+hh]: rows rl+16mb+8hh

    const uint32_t* hU = (const uint32_t*)H;

    // ---------------- 4 flow half-steps ---------------------------------------
    #pragma unroll 1
    for (int s = 0; s < 4; s++) {
        const float* b0sh = biasAll + s*192;
        const float* b1sh = b0sh + 64;
        const float* b2sh = b1sh + 64;
        const float2* w0fp  = (const float2*)gW0f[s]  + lane;
        const float4* w12fp = (const float4*)gW12f[s] + lane;

        const int srcoff = (s & 1) ? 64 : 0;
        const int tgtoff = 64 - srcoff;

        // ======== GEMM0: h = tanh(z_src @ W0^T + b0); A=rna(z), W0=rna ========
        {
            float acc[4][2][4];                 // [nn][mb][4]
            #pragma unroll
            for (int nn = 0; nn < 4; nn++)
                #pragma unroll
                for (int mb = 0; mb < 2; mb++)
                    #pragma unroll
                    for (int v = 0; v < 4; v++) acc[nn][mb][v] = 0.f;

            const int nlim = (warpQ == 1) ? 3 : 4;   // nt7 all-zero: skipped

            #pragma unroll
            for (int kt = 0; kt < 8; kt++) {
                const int kc = srcoff + kt*8 + t;
                uint32_t za[2][4];
                #pragma unroll
                for (int mb = 0; mb < 2; mb++) {
                    const int ra = rl + 16*mb, rb = ra + 8;
                    za[mb][0] = tf32_rna_bits(ZM[ra*ZMSTR + kc]);
                    za[mb][1] = tf32_rna_bits(ZM[rb*ZMSTR + kc]);
                    za[mb][2] = tf32_rna_bits(ZM[ra*ZMSTR + kc+4]);
                    za[mb][3] = tf32_rna_bits(ZM[rb*ZMSTR + kc+4]);
                }
                #pragma unroll
                for (int nn = 0; nn < 4; nn++) {
                    if (nn < nlim) {
                        const float2 w = __ldg(&w0fp[((nt0 + nn)*8 + kt)*32]);
                        const uint32_t b0w = __float_as_uint(w.x);
                        const uint32_t b1w = __float_as_uint(w.y);
                        #pragma unroll
                        for (int mb = 0; mb < 2; mb++)
                            hmma(acc[nn][mb], za[mb][0], za[mb][1], za[mb][2], za[mb][3],
                                 b0w, b1w);
                    }
                }
            }
            // tanh epilogue -> H (tf32-rna). H cols 56..63 (nt7) are never read
            // (GEMM1/2 skips k-tile 7), so nt7 writes are simply omitted.
            const int nlimE = (warpQ == 1) ? 3 : 4;
            #pragma unroll
            for (int nn = 0; nn < 4; nn++) {
                if (nn < nlimE) {
                    const int cb = (nt0 + nn)*8 + 2*t;
                    #pragma unroll
                    for (int mb = 0; mb < 2; mb++) {
                        const int ra = rl + 16*mb, rb = ra + 8;
                        float h00 = tanha(acc[nn][mb][0] + b0sh[cb]);
                        float h01 = tanha(acc[nn][mb][1] + b0sh[cb+1]);
                        float h10 = tanha(acc[nn][mb][2] + b0sh[cb]);
                        float h11 = tanha(acc[nn][mb][3] + b0sh[cb+1]);
                        *(float2*)(H + idx8(ra, cb)) = make_float2(
                            __uint_as_float(tf32_rna_bits(h00)),
                            __uint_as_float(tf32_rna_bits(h01)));
                        *(float2*)(H + idx8(rb, cb)) = make_float2(
                            __uint_as_float(tf32_rna_bits(h10)),
                            __uint_as_float(tf32_rna_bits(h11)));
                    }
                }
            }
        }
        __syncthreads();   // H complete (cross-warp consumption next)

        // ======== GEMM1/2 (single pass, h loaded once per k-tile) ==============
        {
            float am2[4][2][4], av2[4][2][4];   // [nn][mb][4]
            #pragma unroll
            for (int nn = 0; nn < 4; nn++)
                #pragma unroll
                for (int mb = 0; mb < 2; mb++)
                    #pragma unroll
                    for (int v = 0; v < 4; v++) { am2[nn][mb][v] = 0.f; av2[nn][mb][v] = 0.f; }

            #pragma unroll
            for (int kt = 0; kt < 7; kt++) {      // k-tile 7 all-zero: skipped
                const int k0 = kt*8 + t;
                uint32_t hf[2][4];
                #pragma unroll
                for (int mb = 0; mb < 2; mb++) {
                    const int ra = rl + 16*mb, rb = ra + 8;
                    hf[mb][0] = hU[idx8(ra, k0)];
                    hf[mb][1] = hU[idx8(rb, k0)];
                    hf[mb][2] = hU[idx8(ra, k0+4)];
                    hf[mb][3] = hU[idx8(rb, k0+4)];
                }
                #pragma unroll
                for (int nn = 0; nn < 4; nn++) {
                    const float4 w = __ldg(&w12fp[((nt0 + nn)*7 + kt)*32]);
                    const uint32_t c1h0 = __float_as_uint(w.x);
                    const uint32_t c1h1 = __float_as_uint(w.y);
                    const uint32_t c2h0 = __float_as_uint(w.z);
                    const uint32_t c2h1 = __float_as_uint(w.w);
                    #pragma unroll
                    for (int mb = 0; mb < 2; mb++) {
                        hmma(am2[nn][mb], hf[mb][0], hf[mb][1], hf[mb][2], hf[mb][3], c1h0, c1h1);
                        hmma(av2[nn][mb], hf[mb][0], hf[mb][1], hf[mb][2], hf[mb][3], c2h0, c2h1);
                    }
                }
            }
            // update epilogue
            #pragma unroll
            for (int nn = 0; nn < 4; nn++) {
                const int cb = (nt0 + nn)*8 + 2*t;
                #pragma unroll
                for (int mb = 0; mb < 2; mb++) {
                    #pragma unroll
                    for (int hh = 0; hh < 2; hh++) {
                        const int r = rl + 16*mb + 8*hh;
                        const float mew0 = am2[nn][mb][2*hh+0] + b1sh[cb];
                        const float mew1 = am2[nn][mb][2*hh+1] + b1sh[cb+1];
                        const float sr0  = av2[nn][mb][2*hh+0] + b2sh[cb];
                        const float sr1  = av2[nn][mb][2*hh+1] + b2sh[cb+1];
                        const float e0 = __expf(-sr0), e1 = __expf(-sr1);
                        const float o0 = 1.f + e0,     o1 = 1.f + e1;
                        const float g0 = __fdividef(1.f, o0);
                        const float g1 = __fdividef(1.f, o1);
                        lgr[mb*2 + hh] += __log2f(o0) + __log2f(o1);
                        float2 zo = *(const float2*)(ZM + r*ZMSTR + tgtoff + cb);
                        const float zn0 = fmaf(zo.x, g0, mew0);
                        const float zn1 = fmaf(zo.y, g1, mew1);
                        *(float2*)(ZM + r*ZMSTR + tgtoff + cb) = make_float2(zn0, zn1);
                    }
                }
            }
        }
        __syncthreads();   // ZM updated before next step's GEMM0 / final output
    }

    // ---------------- logdet reduce ---------------------------------------------
    #pragma unroll
    for (int i = 0; i < 4; i++) {
        float v = lgr[i];
        v += __shfl_xor_sync(0xFFFFFFFFu, v, 1);
        v += __shfl_xor_sync(0xFFFFFFFFu, v, 2);
        if (t == 0) {
            const int mb = i >> 1, hh = i & 1;
            lgpart[warpQ*128 + warpM*32 + 16*mb + 8*hh + g] = v;
        }
    }
    __syncthreads();

    // ---------------- epilogue: z_out + logpz ----------------------------------
    #pragma unroll 4
    for (int it = 0; it < 64; it++) {
        int j   = it*2 + (tid >> 7);
        int col = tid & 127;
        out[(r0 + j)*ZSv + col] = ZM[j*ZMSTR + col];
    }
    if (tid < 128) {
        float lg = lgpart[tid] + lgpart[128 + tid];
        float logq = -0.5f * ((float)ZSv * 1.8378770664093453f + rsum);
        out[(size_t)ROWS*ZSv + r0 + tid] = logq + 0.69314718055994531f * lg;
    }
}

extern "C" void kernel_launch(void* const* d_in, const int* in_sizes, int n_in,
                              void* d_out, int out_size) {
    (void)in_sizes; (void)n_in; (void)out_size;
    const float* mean   = (const float*)d_in[0];
    const float* logvar = (const float*)d_in[1];
    const float* eps    = (const float*)d_in[2];
    const float* W0     = (const float*)d_in[3];
    const float* b0     = (const float*)d_in[4];
    const float* W1     = (const float*)d_in[5];
    const float* b1     = (const float*)d_in[6];
    const float* W2     = (const float*)d_in[7];
    const float* b2     = (const float*)d_in[8];
    float* out = (float*)d_out;

    flow_prep<<<4, 256>>>(W0, b0, W1, b1, W2, b2);
    cudaFuncSetAttribute(flow_mma11, cudaFuncAttributeMaxDynamicSharedMemorySize, SMEM_BYTES);
    flow_mma11<<<NBLK, TPB, SMEM_BYTES>>>(mean, logvar, eps, out);
}

// round 17
// speedup vs baseline: 2.4769x; 1.1239x over previous
#include <cuda_runtime.h>
#include <cuda_fp16.h>
#include <cstdint>

// Flow1: K=32, B=4096, ZS=128, ZH=64, HS=50, NF=2
#define KK   32
#define BB   4096
#define ZSv  128
#define ZHv  64
#define HSv  50
#define ROWS (KK*BB)          // 131072
#define TPB  256              // 8 warps: 4 M-stripes (32 rows) x 2 N-halves
#define MT   128              // rows per CTA
#define NBLK (ROWS/MT)        // 1024
#define ZMSTR 132             // z master stride (floats)
#define H16STR 36             // h tile stride in f16x2 words (bank 4g+t, conflict-free)

// smem float-index offsets
#define ZM_OFF   0                       // z master [128][132] fp32
#define H16_OFF  (MT*ZMSTR)              // 16896: h tile f16x2 words [128][36]
#define BIAS_OFF (H16_OFF + MT*H16STR)   // 21504: all 4 steps' biases [4][192]
#define LG_OFF   (BIAS_OFF + 768)        // 22272: lgpart [2][128]
#define SMEM_FLOATS (LG_OFF + 256)       // 22528
#define SMEM_BYTES  (SMEM_FLOATS * 4)    // 90112 -> 2 CTAs/SM, ~48KB L1D left
#define RP_OFF   H16_OFF                 // rowpart [128][4] (prologue only)

// pre-converted fp16-packed fragment-major weights (filled by prep each launch)
// gW0h : [nt0..6][kt2 0..3][lane] {b0,b1} f16x2 words   (7*4*32*2 = 1792 floats)
// gW12h: float4 region [nt0..7][kt2 0..2][lane] {w1b0,w1b1,w2b0,w2b1} (3072 floats)
//        + float2 region (k8 tail) [nt0..7][lane] {w1b0,w2b0}         (512 floats)
__device__ __align__(16) float gW0h [4][1792];
__device__ __align__(16) float gW12h[4][3584];
__device__ __align__(16) float gBias[4][192];

__device__ __forceinline__ uint32_t pack_f16x2(float lo, float hi) {
    uint32_t r;  // cvt.f16x2: first source -> high half, second -> low half
    asm("cvt.rn.f16x2.f32 %0, %1, %2;" : "=r"(r) : "f"(hi), "f"(lo));
    return r;
}
__device__ __forceinline__ float tanha(float x) {
    float y; asm("tanh.approx.f32 %0, %1;" : "=f"(y) : "f"(x));
    return y;
}
__device__ __forceinline__ void hmma16(float (&d)[4],
                                       uint32_t a0, uint32_t a1, uint32_t a2, uint32_t a3,
                                       uint32_t b0, uint32_t b1) {
    asm volatile(
        "mma.sync.aligned.m16n8k16.row.col.f32.f16.f16.f32 "
        "{%0,%1,%2,%3}, {%4,%5,%6,%7}, {%8,%9}, {%0,%1,%2,%3};"
        : "+f"(d[0]), "+f"(d[1]), "+f"(d[2]), "+f"(d[3])
        : "r"(a0), "r"(a1), "r"(a2), "r"(a3), "r"(b0), "r"(b1));
}
__device__ __forceinline__ void hmma8(float (&d)[4],
                                      uint32_t a0, uint32_t a1, uint32_t b0) {
    asm volatile(
        "mma.sync.aligned.m16n8k8.row.col.f32.f16.f16.f32 "
        "{%0,%1,%2,%3}, {%4,%5}, {%6}, {%0,%1,%2,%3};"
        : "+f"(d[0]), "+f"(d[1]), "+f"(d[2]), "+f"(d[3])
        : "r"(a0), "r"(a1), "r"(b0));
}
__device__ __forceinline__ float h2bits(float lo, float hi) {
    __half2 p = __floats2half2_rn(lo, hi);   // .x = lo (low half)
    return *reinterpret_cast<float*>(&p);
}

// ---- prep: fp16-pack weights fragment-major (4 CTAs, one per half-step) -----
__global__ void flow_prep(const float* __restrict__ W0, const float* __restrict__ b0,
                          const float* __restrict__ W1, const float* __restrict__ b1,
                          const float* __restrict__ W2, const float* __restrict__ b2)
{
    const int s = blockIdx.x;
    const int tid = threadIdx.x;
    const float* W0g = W0 + s*(HSv*ZHv);
    // GEMM0: i = (nt*4 + kt2)*32 + lane ; K=64 all valid, nt rows >=50 zero
    for (int i = tid; i < 7*4*32; i += blockDim.x) {
        int lane = i & 31, q = i >> 5;
        int kt2 = q & 3, nt = q >> 2;
        int n  = nt*8 + (lane >> 2);
        int k0 = kt2*16 + (lane & 3)*2;
        float v0 = (n < HSv) ? W0g[n*ZHv + k0]     : 0.f;
        float v1 = (n < HSv) ? W0g[n*ZHv + k0 + 1] : 0.f;
        float v2 = (n < HSv) ? W0g[n*ZHv + k0 + 8] : 0.f;
        float v3 = (n < HSv) ? W0g[n*ZHv + k0 + 9] : 0.f;
        gW0h[s][i*2+0] = h2bits(v0, v1);
        gW0h[s][i*2+1] = h2bits(v2, v3);
    }
    const float* W1g = W1 + s*(ZHv*HSv);
    const float* W2g = W2 + s*(ZHv*HSv);
    // GEMM1/2 full k16 tiles: i = (nt*3 + kt2)*32 + lane ; k<=47 all valid
    for (int i = tid; i < 8*3*32; i += blockDim.x) {
        int lane = i & 31, q = i >> 5;
        int kt2 = q % 3, nt = q / 3;
        int n  = nt*8 + (lane >> 2);
        int k0 = kt2*16 + (lane & 3)*2;
        gW12h[s][i*4+0] = h2bits(W1g[n*HSv + k0],     W1g[n*HSv + k0 + 1]);
        gW12h[s][i*4+1] = h2bits(W1g[n*HSv + k0 + 8], W1g[n*HSv + k0 + 9]);
        gW12h[s][i*4+2] = h2bits(W2g[n*HSv + k0],     W2g[n*HSv + k0 + 1]);
        gW12h[s][i*4+3] = h2bits(W2g[n*HSv + k0 + 8], W2g[n*HSv + k0 + 9]);
    }
    // GEMM1/2 k8 tail (k = 48..55; only 48,49 valid): i = nt*32 + lane
    for (int i = tid; i < 8*32; i += blockDim.x) {
        int lane = i & 31;
        int nt = i >> 5;
        int n  = nt*8 + (lane >> 2);
        int k0 = 48 + (lane & 3)*2;
        float a0 = (k0 < HSv)     ? W1g[n*HSv + k0]     : 0.f;
        float a1 = (k0 + 1 < HSv) ? W1g[n*HSv + k0 + 1] : 0.f;
        float c0 = (k0 < HSv)     ? W2g[n*HSv + k0]     : 0.f;
        float c1 = (k0 + 1 < HSv) ? W2g[n*HSv + k0 + 1] : 0.f;
        gW12h[s][3072 + i*2+0] = h2bits(a0, a1);
        gW12h[s][3072 + i*2+1] = h2bits(c0, c1);
    }
    if (tid < 64) {
        gBias[s][tid]       = (tid < HSv) ? b0[s*HSv + tid] : 0.f;
        gBias[s][64 + tid]  = b1[s*ZHv + tid];
        gBias[s][128 + tid] = b2[s*ZHv + tid];
    }
}

// ---- main flow kernel --------------------------------------------------------
__global__ void __launch_bounds__(TPB, 2) flow_mma12(
    const float* __restrict__ mean, const float* __restrict__ logvar,
    const float* __restrict__ eps, float* __restrict__ out)
{
    extern __shared__ float sm[];
    float*    ZM      = sm + ZM_OFF;
    uint32_t* H16u    = (uint32_t*)(sm + H16_OFF);
    float*    biasAll = sm + BIAS_OFF;
    float*    lgpart  = sm + LG_OFF;
    float*    rowpart = sm + RP_OFF;

    const int tid   = threadIdx.x;
    const int lane  = tid & 31;
    const int warp  = tid >> 5;
    const int warpM = warp & 3;        // M stripe (32 rows)
    const int warpQ = warp >> 2;       // N half (4 n-tiles)
    const int g     = lane >> 2;
    const int t     = lane & 3;
    const int rl    = warpM * 32 + g;  // m16 blocks at rl(+8) and rl+16(+24)
    const int nt0   = warpQ * 4;
    const size_t r0    = (size_t)blockIdx.x * MT;
    const size_t bbase = (size_t)(r0 & (BB-1)) * ZSv;

    // ---------------- prologue: bias stage + z init + rowsum -------------------
    for (int i = tid; i < 768; i += TPB)
        biasAll[i] = ((const float*)gBias)[i];

    #pragma unroll 4
    for (int it = 0; it < 64; it++) {
        int j   = it*2 + (tid >> 7);
        int col = tid & 127;
        size_t go = (size_t)j * ZSv + col;
        float ep = eps[r0*ZSv + go];
        float lv = logvar[bbase + go];
        float mn = mean[bbase + go];
        ZM[j*ZMSTR + col] = fmaf(ep, __expf(0.5f*lv), mn);
        float c = fmaf(ep, ep, lv);
        #pragma unroll
        for (int o = 16; o; o >>= 1) c += __shfl_xor_sync(0xFFFFFFFFu, c, o);
        if (lane == 0) rowpart[j*4 + ((tid >> 5) & 3)] = c;
    }
    __syncthreads();
    float rsum = 0.f;
    if (tid < 128)
        rsum = rowpart[tid*4+0] + rowpart[tid*4+1] + rowpart[tid*4+2] + rowpart[tid*4+3];
    __syncthreads();   // rowpart region (H16) reused below

    float lgr[4] = {0.f, 0.f, 0.f, 0.f};   // [mb*2+hh]: rows rl+16mb+8hh

    // ---------------- 4 flow half-steps ---------------------------------------
    #pragma unroll 1
    for (int s = 0; s < 4; s++) {
        const float* b0sh = biasAll + s*192;
        const float* b1sh = b0sh + 64;
        const float* b2sh = b1sh + 64;
        const float2* w0p   = (const float2*)gW0h[s];
        const float4* w12p4 = (const float4*)gW12h[s];
        const float2* w12p2 = (const float2*)(gW12h[s] + 3072);

        const int srcoff = (s & 1) ? 64 : 0;
        const int tgtoff = 64 - srcoff;

        // ======== GEMM0 (fp16 k16): h = tanh(z_src @ W0^T + b0) ================
        {
            float acc[4][2][4];                 // [nn][mb][4]
            #pragma unroll
            for (int nn = 0; nn < 4; nn++)
                #pragma unroll
                for (int mb = 0; mb < 2; mb++)
                    #pragma unroll
                    for (int v = 0; v < 4; v++) acc[nn][mb][v] = 0.f;

            const int nlim = (warpQ == 1) ? 3 : 4;   // nt7 all-zero: skipped

            #pragma unroll
            for (int kt2 = 0; kt2 < 4; kt2++) {
                const int kb = srcoff + kt2*16 + 2*t;
                uint32_t za[2][4];
                #pragma unroll
                for (int mb = 0; mb < 2; mb++) {
                    const int ra = rl + 16*mb, rb = ra + 8;
                    za[mb][0] = pack_f16x2(ZM[ra*ZMSTR + kb],     ZM[ra*ZMSTR + kb + 1]);
                    za[mb][1] = pack_f16x2(ZM[rb*ZMSTR + kb],     ZM[rb*ZMSTR + kb + 1]);
                    za[mb][2] = pack_f16x2(ZM[ra*ZMSTR + kb + 8], ZM[ra*ZMSTR + kb + 9]);
                    za[mb][3] = pack_f16x2(ZM[rb*ZMSTR + kb + 8], ZM[rb*ZMSTR + kb + 9]);
                }
                #pragma unroll
                for (int nn = 0; nn < 4; nn++) {
                    if (nn < nlim) {
                        const float2 w = __ldg(&w0p[(((nt0 + nn)*4 + kt2)*32) + lane]);
                        const uint32_t b0w = __float_as_uint(w.x);
                        const uint32_t b1w = __float_as_uint(w.y);
                        #pragma unroll
                        for (int mb = 0; mb < 2; mb++)
                            hmma16(acc[nn][mb], za[mb][0], za[mb][1], za[mb][2], za[mb][3],
                                   b0w, b1w);
                    }
                }
            }
            // tanh epilogue -> H16 (f16x2 words); nt7 never written (never read)
            const int nlimE = (warpQ == 1) ? 3 : 4;
            #pragma unroll
            for (int nn = 0; nn < 4; nn++) {
                if (nn < nlimE) {
                    const int cb = (nt0 + nn)*8 + 2*t;   // column pair base
                    const int wc = (nt0 + nn)*4 + t;     // word col = cb/2
                    #pragma unroll
                    for (int mb = 0; mb < 2; mb++) {
                        const int ra = rl + 16*mb, rb = ra + 8;
                        float h00 = tanha(acc[nn][mb][0] + b0sh[cb]);
                        float h01 = tanha(acc[nn][mb][1] + b0sh[cb+1]);
                        float h10 = tanha(acc[nn][mb][2] + b0sh[cb]);
                        float h11 = tanha(acc[nn][mb][3] + b0sh[cb+1]);
                        H16u[ra*H16STR + wc] = pack_f16x2(h00, h01);
                        H16u[rb*H16STR + wc] = pack_f16x2(h10, h11);
                    }
                }
            }
        }
        __syncthreads();   // H16 complete (cross-warp consumption next)

        // ======== GEMM1/2 (fp16 3x k16 + 1x k8): mew, sr ; update + logdet =====
        {
            float am2[4][2][4], av2[4][2][4];   // [nn][mb][4]
            #pragma unroll
            for (int nn = 0; nn < 4; nn++)
                #pragma unroll
                for (int mb = 0; mb < 2; mb++)
                    #pragma unroll
                    for (int v = 0; v < 4; v++) { am2[nn][mb][v] = 0.f; av2[nn][mb][v] = 0.f; }

            #pragma unroll
            for (int kt2 = 0; kt2 < 3; kt2++) {    // k 0..47
                uint32_t hw[2][4];
                #pragma unroll
                for (int mb = 0; mb < 2; mb++) {
                    const int ra = rl + 16*mb, rb = ra + 8;
                    hw[mb][0] = H16u[ra*H16STR + 8*kt2 + t];
                    hw[mb][1] = H16u[rb*H16STR + 8*kt2 + t];
                    hw[mb][2] = H16u[ra*H16STR + 8*kt2 + t + 4];
                    hw[mb][3] = H16u[rb*H16STR + 8*kt2 + t + 4];
                }
                #pragma unroll
                for (int nn = 0; nn < 4; nn++) {
                    const float4 w = __ldg(&w12p4[(((nt0 + nn)*3 + kt2)*32) + lane]);
                    const uint32_t w1b0 = __float_as_uint(w.x);
                    const uint32_t w1b1 = __float_as_uint(w.y);
                    const uint32_t w2b0 = __float_as_uint(w.z);
                    const uint32_t w2b1 = __float_as_uint(w.w);
                    #pragma unroll
                    for (int mb = 0; mb < 2; mb++) {
                        hmma16(am2[nn][mb], hw[mb][0], hw[mb][1], hw[mb][2], hw[mb][3],
                               w1b0, w1b1);
                        hmma16(av2[nn][mb], hw[mb][0], hw[mb][1], hw[mb][2], hw[mb][3],
                               w2b0, w2b1);
                    }
                }
            }
            {   // k8 tail: k 48..55
                uint32_t hw0[2], hw1[2];
                #pragma unroll
                for (int mb = 0; mb < 2; mb++) {
                    const int ra = rl + 16*mb, rb = ra + 8;
                    hw0[mb] = H16u[ra*H16STR + 24 + t];
                    hw1[mb] = H16u[rb*H16STR + 24 + t];
                }
                #pragma unroll
                for (int nn = 0; nn < 4; nn++) {
                    const float2 w = __ldg(&w12p2[(nt0 + nn)*32 + lane]);
                    const uint32_t w1b = __float_as_uint(w.x);
                    const uint32_t w2b = __float_as_uint(w.y);
                    #pragma unroll
                    for (int mb = 0; mb < 2; mb++) {
                        hmma8(am2[nn][mb], hw0[mb], hw1[mb], w1b);
                        hmma8(av2[nn][mb], hw0[mb], hw1[mb], w2b);
                    }
                }
            }
            // update epilogue
            #pragma unroll
            for (int nn = 0; nn < 4; nn++) {
                const int cb = (nt0 + nn)*8 + 2*t;
                #pragma unroll
                for (int mb = 0; mb < 2; mb++) {
                    #pragma unroll
                    for (int hh = 0; hh < 2; hh++) {
                        const int r = rl + 16*mb + 8*hh;
                        const float mew0 = am2[nn][mb][2*hh+0] + b1sh[cb];
                        const float mew1 = am2[nn][mb][2*hh+1] + b1sh[cb+1];
                        const float sr0  = av2[nn][mb][2*hh+0] + b2sh[cb];
                        const float sr1  = av2[nn][mb][2*hh+1] + b2sh[cb+1];
                        const float e0 = __expf(-sr0), e1 = __expf(-sr1);
                        const float o0 = 1.f + e0,     o1 = 1.f + e1;
                        const float g0 = __fdividef(1.f, o0);
                        const float g1 = __fdividef(1.f, o1);
                        lgr[mb*2 + hh] += __log2f(o0) + __log2f(o1);
                        float2 zo = *(const float2*)(ZM + r*ZMSTR + tgtoff + cb);
                        const float zn0 = fmaf(zo.x, g0, mew0);
                        const float zn1 = fmaf(zo.y, g1, mew1);
                        *(float2*)(ZM + r*ZMSTR + tgtoff + cb) = make_float2(zn0, zn1);
                    }
                }
            }
        }
        __syncthreads();   // ZM updated before next step's GEMM0 / final output
    }

    // ---------------- logdet reduce ---------------------------------------------
    #pragma unroll
    for (int i = 0; i < 4; i++) {
        float v = lgr[i];
        v += __shfl_xor_sync(0xFFFFFFFFu, v, 1);
        v += __shfl_xor_sync(0xFFFFFFFFu, v, 2);
        if (t == 0) {
            const int mb = i >> 1, hh = i & 1;
            lgpart[warpQ*128 + warpM*32 + 16*mb + 8*hh + g] = v;
        }
    }
    __syncthreads();

    // ---------------- epilogue: z_out + logpz ----------------------------------
    #pragma unroll 4
    for (int it = 0; it < 64; it++) {
        int j   = it*2 + (tid >> 7);
        int col = tid & 127;
        out[(r0 + j)*ZSv + col] = ZM[j*ZMSTR + col];
    }
    if (tid < 128) {
        float lg = lgpart[tid] + lgpart[128 + tid];
        float logq = -0.5f * ((float)ZSv * 1.8378770664093453f + rsum);
        out[(size_t)ROWS*ZSv + r0 + tid] = logq + 0.69314718055994531f * lg;
    }
}

extern "C" void kernel_launch(void* const* d_in, const int* in_sizes, int n_in,
                              void* d_out, int out_size) {
    (void)in_sizes; (void)n_in; (void)out_size;
    const float* mean   = (const float*)d_in[0];
    const float* logvar = (const float*)d_in[1];
    const float* eps    = (const float*)d_in[2];
    const float* W0     = (const float*)d_in[3];
    const float* b0     = (const float*)d_in[4];
    const float* W1     = (const float*)d_in[5];
    const float* b1     = (const float*)d_in[6];
    const float* W2     = (const float*)d_in[7];
    const float* b2     = (const float*)d_in[8];
    float* out = (float*)d_out;

    flow_prep<<<4, 256>>>(W0, b0, W1, b1, W2, b2);
    cudaFuncSetAttribute(flow_mma12, cudaFuncAttributeMaxDynamicSharedMemorySize, SMEM_BYTES);
    flow_mma12<<<NBLK, TPB, SMEM_BYTES>>>(mean, logvar, eps, out);
}